// round 4
// baseline (speedup 1.0000x reference)
#include <cuda_runtime.h>
#include <math.h>

#define NN 50000
#define NE 600000
#define DD 128
#define AVG_D_LOG_F 1.6094379124341003f  /* log(5) */

// ---------------- scratch (static device arrays; no runtime alloc) --------
__device__ float g_P[NN * DD];          // h @ W_pre[0:128]
__device__ float g_Q[NN * DD];          // h @ W_pre[128:256] + b_pre
__device__ float g_agg[NN * 4 * DD];    // [mean, max, min, std] per node
__device__ float g_Y[NN * 3 * DD];      // agg @ Bcat  (identity / amp / att)
__device__ float g_H0[NN * DD];         // h @ W_post[0:128]
__device__ float g_hp[NN * DD];         // posttrans output
__device__ float g_B2[512 * 384];       // repacked W_post columns
__device__ float g_sa[NN], g_sb[NN];    // per-node scalers
__device__ int   g_cnt[NN], g_cur[NN];
__device__ int   g_rowptr[NN + 1];
__device__ int   g_eid[NE];
__device__ int   g_srcs[NE];
__device__ int   g_stride;              // 1 if edge arrays are int32, 2 if int64

// ---------------- f32x2 helpers (Blackwell packed fp32 pipe) ---------------
__device__ __forceinline__ unsigned long long pack2(float lo, float hi) {
    unsigned long long r;
    asm("mov.b64 %0, {%1, %2};" : "=l"(r) : "f"(lo), "f"(hi));
    return r;
}
__device__ __forceinline__ void unpack2(unsigned long long v, float& lo, float& hi) {
    asm("mov.b64 {%0, %1}, %2;" : "=f"(lo), "=f"(hi) : "l"(v));
}
__device__ __forceinline__ void ffma2(unsigned long long& d, unsigned long long a,
                                      unsigned long long b) {
    asm("fma.rn.f32x2 %0, %1, %2, %0;" : "+l"(d) : "l"(a), "l"(b));
}

// ---------------- dtype detection ------------------------------------------
// edge_dst is guaranteed to start with arange(N): [0,1,2,...].
// int32 buffer reads [0,1,2]; int64 (little-endian) reads [0,0,1].
__global__ void detect_kernel(const int* __restrict__ edst32) {
    g_stride = (edst32[1] == 1) ? 1 : 2;
}

// ---------------- CSR build ------------------------------------------------
__global__ void zero_kernel() {
    int i = blockIdx.x * blockDim.x + threadIdx.x;
    if (i < NN) { g_cnt[i] = 0; g_cur[i] = 0; }
}

__global__ void hist_kernel(const int* __restrict__ edst) {
    int i = blockIdx.x * blockDim.x + threadIdx.x;
    if (i < NE) atomicAdd(&g_cnt[edst[(size_t)i * g_stride]], 1);
}

__global__ void scan_kernel() {
    __shared__ int sh[1024];
    const int t = threadIdx.x;
    const int C = (NN + 1023) / 1024;
    int beg = t * C, end = min(beg + C, NN);
    int s = 0;
    for (int i = beg; i < end; i++) s += g_cnt[i];
    sh[t] = s;
    __syncthreads();
    for (int off = 1; off < 1024; off <<= 1) {
        int v = (t >= off) ? sh[t - off] : 0;
        __syncthreads();
        sh[t] += v;
        __syncthreads();
    }
    int run = (t == 0) ? 0 : sh[t - 1];
    for (int i = beg; i < end; i++) { g_rowptr[i] = run; run += g_cnt[i]; }
    if (t == 1023) g_rowptr[NN] = sh[1023];
}

__global__ void scatter_kernel(const int* __restrict__ edst) {
    int i = blockIdx.x * blockDim.x + threadIdx.x;
    if (i >= NE) return;
    int d = edst[(size_t)i * g_stride];
    int pos = atomicAdd(&g_cur[d], 1);
    g_eid[g_rowptr[d] + pos] = i;
}

// Sort each node's edge list by edge id (deterministic float-sum order),
// then materialize the src indices.
__global__ void sortsrc_kernel(const int* __restrict__ esrc) {
    int n = blockIdx.x * blockDim.x + threadIdx.x;
    if (n >= NN) return;
    int st = g_stride;
    int s = g_rowptr[n], e = g_rowptr[n + 1];
    for (int i = s + 1; i < e; i++) {
        int key = g_eid[i];
        int j = i - 1;
        while (j >= s && g_eid[j] > key) { g_eid[j + 1] = g_eid[j]; j--; }
        g_eid[j + 1] = key;
    }
    for (int i = s; i < e; i++) g_srcs[i] = esrc[(size_t)g_eid[i] * st];
}

// ---------------- repack W_post columns into Bcat[512][384] ----------------
// cols [0,128): identity block = W_post rows 128+k
// cols [128,256): amplification block = rows 640+k
// cols [256,384): attenuation block  = rows 1152+k
__global__ void repack_kernel(const float* __restrict__ W_post) {
    int idx = blockIdx.x * blockDim.x + threadIdx.x;
    if (idx >= 512 * 384) return;
    int k = idx / 384, j = idx % 384;
    int s = j >> 7, jj = j & 127;
    g_B2[idx] = W_post[(size_t)(128 + s * 512 + k) * 128 + jj];
}

// ---------------- SGEMM: C[M,*] = A[M,K] @ B[K,*], fp32 via FFMA2 ----------
// 128x128x16 tiles, 256 threads, 8x8 per thread, packed f32x2 accumulators.
// mode 0: C = acc
// mode 1: C = acc + bias[col]
// mode 2: C = res[row,col] + leaky_relu(acc + bias[col])
__global__ __launch_bounds__(256)
void sgemm_kernel(const float* __restrict__ A, int lda,
                  const float* __restrict__ B, int ldb,
                  float* __restrict__ C, int ldc,
                  int M, int K, int mode,
                  const float* __restrict__ bias,
                  const float* __restrict__ res) {
    __shared__ float As[16][128];  // transposed A tile
    __shared__ float Bs[16][128];
    const int tid = threadIdx.x;
    const int brow = blockIdx.x * 128;
    const int bcol = blockIdx.y * 128;
    const int tr = (tid >> 4) * 8;
    const int tc = (tid & 15) * 8;

    unsigned long long acc[8][4];
#pragma unroll
    for (int i = 0; i < 8; i++)
#pragma unroll
        for (int j = 0; j < 4; j++) acc[i][j] = 0ull;

    for (int k0 = 0; k0 < K; k0 += 16) {
#pragma unroll
        for (int l = 0; l < 2; l++) {
            int q = tid + l * 256;
            int r = q >> 2;
            int kc = (q & 3) << 2;
            float4 v = make_float4(0.f, 0.f, 0.f, 0.f);
            int grow = brow + r;
            if (grow < M) v = *(const float4*)&A[(size_t)grow * lda + k0 + kc];
            As[kc + 0][r] = v.x; As[kc + 1][r] = v.y;
            As[kc + 2][r] = v.z; As[kc + 3][r] = v.w;
        }
#pragma unroll
        for (int l = 0; l < 2; l++) {
            int q = tid + l * 256;
            int kr = q >> 5;
            int c4 = (q & 31) << 2;
            *(float4*)&Bs[kr][c4] = *(const float4*)&B[(size_t)(k0 + kr) * ldb + bcol + c4];
        }
        __syncthreads();
#pragma unroll
        for (int k = 0; k < 16; k++) {
            float4 a0 = *(const float4*)&As[k][tr];
            float4 a1 = *(const float4*)&As[k][tr + 4];
            unsigned long long ap[8];
            ap[0] = pack2(a0.x, a0.x); ap[1] = pack2(a0.y, a0.y);
            ap[2] = pack2(a0.z, a0.z); ap[3] = pack2(a0.w, a0.w);
            ap[4] = pack2(a1.x, a1.x); ap[5] = pack2(a1.y, a1.y);
            ap[6] = pack2(a1.z, a1.z); ap[7] = pack2(a1.w, a1.w);
            float4 b0 = *(const float4*)&Bs[k][tc];
            float4 b1 = *(const float4*)&Bs[k][tc + 4];
            unsigned long long bp[4];
            bp[0] = pack2(b0.x, b0.y); bp[1] = pack2(b0.z, b0.w);
            bp[2] = pack2(b1.x, b1.y); bp[3] = pack2(b1.z, b1.w);
#pragma unroll
            for (int i = 0; i < 8; i++) {
                ffma2(acc[i][0], ap[i], bp[0]);
                ffma2(acc[i][1], ap[i], bp[1]);
                ffma2(acc[i][2], ap[i], bp[2]);
                ffma2(acc[i][3], ap[i], bp[3]);
            }
        }
        __syncthreads();
    }

#pragma unroll
    for (int i = 0; i < 8; i++) {
        int row = brow + tr + i;
        if (row >= M) continue;
        float o[8];
#pragma unroll
        for (int j = 0; j < 4; j++) unpack2(acc[i][j], o[2 * j], o[2 * j + 1]);
        if (mode == 1) {
#pragma unroll
            for (int j = 0; j < 8; j++) o[j] += bias[bcol + tc + j];
        } else if (mode == 2) {
#pragma unroll
            for (int j = 0; j < 8; j++) {
                float v = o[j] + bias[bcol + tc + j];
                v = (v > 0.f) ? v : 0.01f * v;
                o[j] = res[(size_t)row * ldc + bcol + tc + j] + v;
            }
        }
        float4* cp = (float4*)&C[(size_t)row * ldc + bcol + tc];
        cp[0] = make_float4(o[0], o[1], o[2], o[3]);
        cp[1] = make_float4(o[4], o[5], o[6], o[7]);
    }
}

// ---------------- per-node multi-aggregator reduce -------------------------
// one warp per node; lane handles 4 features (float4).
__global__ __launch_bounds__(256)
void aggregate_kernel() {
    int gw = (blockIdx.x * blockDim.x + threadIdx.x) >> 5;
    int lane = threadIdx.x & 31;
    if (gw >= NN) return;
    const float4* P4 = (const float4*)g_P;
    const float4* Q4 = (const float4*)g_Q;
    float4 q = Q4[(size_t)gw * 32 + lane];
    int s = g_rowptr[gw], e = g_rowptr[gw + 1];
    float4 sm = make_float4(0.f, 0.f, 0.f, 0.f);
    float4 ss = make_float4(0.f, 0.f, 0.f, 0.f);
    float4 mx = make_float4(-3.4e38f, -3.4e38f, -3.4e38f, -3.4e38f);
    float4 mn = make_float4(3.4e38f, 3.4e38f, 3.4e38f, 3.4e38f);
    for (int i = s; i < e; i++) {
        int src = g_srcs[i];
        float4 p = P4[(size_t)src * 32 + lane];
        float ex = fmaxf(p.x + q.x, 0.f);
        float ey = fmaxf(p.y + q.y, 0.f);
        float ez = fmaxf(p.z + q.z, 0.f);
        float ew = fmaxf(p.w + q.w, 0.f);
        sm.x += ex; sm.y += ey; sm.z += ez; sm.w += ew;
        ss.x += ex * ex; ss.y += ey * ey; ss.z += ez * ez; ss.w += ew * ew;
        mx.x = fmaxf(mx.x, ex); mx.y = fmaxf(mx.y, ey);
        mx.z = fmaxf(mx.z, ez); mx.w = fmaxf(mx.w, ew);
        mn.x = fminf(mn.x, ex); mn.y = fminf(mn.y, ey);
        mn.z = fminf(mn.z, ez); mn.w = fminf(mn.w, ew);
    }
    float deg = (float)(e - s);       // >= 1 (self-loops guaranteed)
    float inv = 1.0f / deg;
    float4 mean = make_float4(sm.x * inv, sm.y * inv, sm.z * inv, sm.w * inv);
    float4 msq  = make_float4(ss.x * inv, ss.y * inv, ss.z * inv, ss.w * inv);
    float4 sd;
    sd.x = sqrtf(fmaxf(msq.x - mean.x * mean.x, 0.f) + 1e-5f);
    sd.y = sqrtf(fmaxf(msq.y - mean.y * mean.y, 0.f) + 1e-5f);
    sd.z = sqrtf(fmaxf(msq.z - mean.z * mean.z, 0.f) + 1e-5f);
    sd.w = sqrtf(fmaxf(msq.w - mean.w * mean.w, 0.f) + 1e-5f);
    float4* out = (float4*)(g_agg + (size_t)gw * 512);
    out[lane]      = mean;
    out[32 + lane] = mx;
    out[64 + lane] = mn;
    out[96 + lane] = sd;
    if (lane == 0) {
        float ld = logf(deg + 1.0f);
        g_sa[gw] = ld * (1.0f / AVG_D_LOG_F);
        g_sb[gw] = AVG_D_LOG_F / ld;
    }
}

// ---------------- combine: hp = relu(H0 + Y0 + a*Y1 + b*Y2 + b_post) -------
__global__ void combine_kernel(const float* __restrict__ b_post) {
    int idx = blockIdx.x * blockDim.x + threadIdx.x;
    if (idx >= NN * 32) return;
    int n = idx >> 5, l = idx & 31;
    const float4* H04 = (const float4*)g_H0;
    const float4* Y4 = (const float4*)g_Y;
    const float4* bp4 = (const float4*)b_post;
    float a = g_sa[n], b = g_sb[n];
    float4 h0 = H04[idx];
    float4 y0 = Y4[(size_t)n * 96 + l];
    float4 y1 = Y4[(size_t)n * 96 + 32 + l];
    float4 y2 = Y4[(size_t)n * 96 + 64 + l];
    float4 bb = bp4[l];
    float4 v;
    v.x = fmaxf(h0.x + y0.x + a * y1.x + b * y2.x + bb.x, 0.f);
    v.y = fmaxf(h0.y + y0.y + a * y1.y + b * y2.y + bb.y, 0.f);
    v.z = fmaxf(h0.z + y0.z + a * y1.z + b * y2.z + bb.z, 0.f);
    v.w = fmaxf(h0.w + y0.w + a * y1.w + b * y2.w + bb.w, 0.f);
    ((float4*)g_hp)[idx] = v;
}

// ---------------- launch ---------------------------------------------------
extern "C" void kernel_launch(void* const* d_in, const int* in_sizes, int n_in,
                              void* d_out, int out_size) {
    const float* h      = (const float*)d_in[0];
    const int*   esrc   = (const int*)d_in[1];   // int32 (JAX x64 off) or int64 — detected
    const int*   edst   = (const int*)d_in[2];
    const float* W_pre  = (const float*)d_in[3];
    const float* b_pre  = (const float*)d_in[4];
    const float* W_post = (const float*)d_in[5];
    const float* b_post = (const float*)d_in[6];
    const float* W_mix  = (const float*)d_in[7];
    const float* b_mix  = (const float*)d_in[8];
    float*       out    = (float*)d_out;

    float *P, *Q, *AGG, *Y, *H0, *HP, *B2;
    cudaGetSymbolAddress((void**)&P,   g_P);
    cudaGetSymbolAddress((void**)&Q,   g_Q);
    cudaGetSymbolAddress((void**)&AGG, g_agg);
    cudaGetSymbolAddress((void**)&Y,   g_Y);
    cudaGetSymbolAddress((void**)&H0,  g_H0);
    cudaGetSymbolAddress((void**)&HP,  g_hp);
    cudaGetSymbolAddress((void**)&B2,  g_B2);

    // dtype detect + CSR build (deterministic: per-node lists sorted by edge id)
    detect_kernel<<<1, 1>>>(edst);
    zero_kernel<<<(NN + 255) / 256, 256>>>();
    hist_kernel<<<(NE + 255) / 256, 256>>>(edst);
    scan_kernel<<<1, 1024>>>();
    scatter_kernel<<<(NE + 255) / 256, 256>>>(edst);
    sortsrc_kernel<<<(NN + 127) / 128, 128>>>(esrc);
    repack_kernel<<<(512 * 384 + 255) / 256, 256>>>(W_post);

    dim3 g1((NN + 127) / 128, 1);
    // P = h @ W_pre[0:128];  Q = h @ W_pre[128:256] + b_pre
    sgemm_kernel<<<g1, 256>>>(h, 128, W_pre, 128, P, 128, NN, 128, 0, nullptr, nullptr);
    sgemm_kernel<<<g1, 256>>>(h, 128, W_pre + 128 * 128, 128, Q, 128, NN, 128, 1, b_pre, nullptr);

    aggregate_kernel<<<(NN + 7) / 8, 256>>>();

    // Y = agg @ Bcat  (the big one: 50000 x 512 x 384)
    dim3 g2((NN + 127) / 128, 3);
    sgemm_kernel<<<g2, 256>>>(AGG, 512, B2, 384, Y, 384, NN, 512, 0, nullptr, nullptr);
    // H0 = h @ W_post[0:128]
    sgemm_kernel<<<g1, 256>>>(h, 128, W_post, 128, H0, 128, NN, 128, 0, nullptr, nullptr);

    combine_kernel<<<(NN * 32 + 255) / 256, 256>>>(b_post);

    // out = h + leaky_relu(hp @ W_mix + b_mix)
    sgemm_kernel<<<g1, 256>>>(HP, 128, W_mix, 128, out, 128, NN, 128, 2, b_mix, h);
}

// round 6
// speedup vs baseline: 2.0998x; 2.0998x over previous
#include <cuda_runtime.h>
#include <math.h>
#include <stdint.h>

#define NN 50000
#define NE 600000
#define DD 128
#define AVG_D_LOG_F 1.6094379124341003f  /* log(5) */

// ---------------- scratch (static device arrays; no runtime alloc) --------
__device__ float g_P[NN * DD];          // h @ W_pre[0:128]
__device__ float g_Q[NN * DD];          // h @ W_pre[128:256] + b_pre
__device__ float g_agg[NN * 4 * DD];    // [mean, max, min, std] per node
__device__ float g_Y[NN * 3 * DD];      // agg @ Bcat (identity / amp / att)
__device__ float g_H0[NN * DD];         // h @ W_post[0:128]
__device__ float g_hp[NN * DD];         // posttrans output
__device__ float g_B2[512 * 384];       // repacked W_post columns
__device__ float g_sa[NN], g_sb[NN];    // per-node scalers
__device__ int   g_cnt[NN], g_cur[NN];
__device__ int   g_rowptr[NN + 1];
__device__ int   g_part[256];
__device__ int   g_eid[NE];
__device__ int   g_srcs[NE];
__device__ int   g_stride;              // 1 if edge arrays int32, 2 if int64

// ---------------- dtype detection ------------------------------------------
// edge_dst starts with arange(N): int32 reads [0,1,2]; int64 LE reads [0,0,1].
__global__ void detect_kernel(const int* __restrict__ edst32) {
    g_stride = (edst32[1] == 1) ? 1 : 2;
}

// ---------------- CSR build ------------------------------------------------
__global__ void zero_kernel() {
    int i = blockIdx.x * blockDim.x + threadIdx.x;
    if (i < NN) { g_cnt[i] = 0; g_cur[i] = 0; }
}

__global__ void hist_kernel(const int* __restrict__ edst) {
    int i = blockIdx.x * blockDim.x + threadIdx.x;
    if (i < NE) atomicAdd(&g_cnt[edst[(size_t)i * g_stride]], 1);
}

// 3-phase multiblock exclusive scan of g_cnt -> g_rowptr
__global__ void scan1_kernel() {          // per-block sums
    __shared__ int sh[256];
    int t = threadIdx.x, b = blockIdx.x;
    int i = b * 256 + t;
    sh[t] = (i < NN) ? g_cnt[i] : 0;
    __syncthreads();
    for (int off = 128; off > 0; off >>= 1) {
        if (t < off) sh[t] += sh[t + off];
        __syncthreads();
    }
    if (t == 0) g_part[b] = sh[0];
}

__global__ void scan2_kernel(int nblk) {  // exclusive scan of partials
    __shared__ int sh[256];
    int t = threadIdx.x;
    int v = (t < nblk) ? g_part[t] : 0;
    sh[t] = v;
    __syncthreads();
    for (int off = 1; off < 256; off <<= 1) {
        int u = (t >= off) ? sh[t - off] : 0;
        __syncthreads();
        sh[t] += u;
        __syncthreads();
    }
    if (t < nblk) g_part[t] = sh[t] - v;  // exclusive
}

__global__ void scan3_kernel() {          // local scan + offset
    __shared__ int sh[256];
    int t = threadIdx.x, b = blockIdx.x;
    int i = b * 256 + t;
    int c = (i < NN) ? g_cnt[i] : 0;
    sh[t] = c;
    __syncthreads();
    for (int off = 1; off < 256; off <<= 1) {
        int u = (t >= off) ? sh[t - off] : 0;
        __syncthreads();
        sh[t] += u;
        __syncthreads();
    }
    if (i < NN) g_rowptr[i] = g_part[b] + sh[t] - c;  // exclusive
    if (b == 0 && t == 0) g_rowptr[NN] = NE;
}

__global__ void scatter_kernel(const int* __restrict__ edst) {
    int i = blockIdx.x * blockDim.x + threadIdx.x;
    if (i >= NE) return;
    int d = edst[(size_t)i * g_stride];
    int pos = atomicAdd(&g_cur[d], 1);
    g_eid[g_rowptr[d] + pos] = i;
}

// Sort each node's edge list by edge id (deterministic sum order), then
// materialize src indices.
__global__ void sortsrc_kernel(const int* __restrict__ esrc) {
    int n = blockIdx.x * blockDim.x + threadIdx.x;
    if (n >= NN) return;
    int st = g_stride;
    int s = g_rowptr[n], e = g_rowptr[n + 1];
    for (int i = s + 1; i < e; i++) {
        int key = g_eid[i];
        int j = i - 1;
        while (j >= s && g_eid[j] > key) { g_eid[j + 1] = g_eid[j]; j--; }
        g_eid[j + 1] = key;
    }
    for (int i = s; i < e; i++) g_srcs[i] = esrc[(size_t)g_eid[i] * st];
}

// ---------------- repack W_post columns into Bcat[512][384] ----------------
__global__ void repack_kernel(const float* __restrict__ W_post) {
    int idx = blockIdx.x * blockDim.x + threadIdx.x;
    if (idx >= 512 * 384) return;
    int k = idx / 384, j = idx % 384;
    int s = j >> 7, jj = j & 127;
    g_B2[idx] = W_post[(size_t)(128 + s * 512 + k) * 128 + jj];
}

// ---------------- tf32 MMA GEMM -------------------------------------------
// C[M,N] = A[M,K] @ B[K,N], 128x128x32 tiles, 256 threads (8 warps 2x4),
// warp tile 64x32 via mma.sync.m16n8k8 tf32 (RNA-rounded inputs).
// mode 0: C = acc; 1: C = acc + bias; 2: C = res + leaky_relu(acc + bias)
__device__ __forceinline__ uint32_t f2tf32(float f) {
    uint32_t u;
    asm("cvt.rna.tf32.f32 %0, %1;" : "=r"(u) : "f"(f));
    return u;
}
__device__ __forceinline__ void mma_tf32(float* d, const uint32_t* a,
                                         const uint32_t* b) {
    asm volatile(
        "mma.sync.aligned.m16n8k8.row.col.f32.tf32.tf32.f32 "
        "{%0,%1,%2,%3}, {%4,%5,%6,%7}, {%8,%9}, {%0,%1,%2,%3};"
        : "+f"(d[0]), "+f"(d[1]), "+f"(d[2]), "+f"(d[3])
        : "r"(a[0]), "r"(a[1]), "r"(a[2]), "r"(a[3]), "r"(b[0]), "r"(b[1]));
}

#define AS_STRIDE 36   /* [m][k]: (4r+c+8g)%32 conflict-free frag loads */
#define BS_STRIDE 136  /* [k][n]: (8c+r)%32 conflict-free frag loads */

__global__ __launch_bounds__(256, 2)
void mma_gemm(const float* __restrict__ A, int lda,
              const float* __restrict__ B, int ldb,
              float* __restrict__ C, int ldc,
              int M, int K, int mode,
              const float* __restrict__ bias,
              const float* __restrict__ res) {
    __shared__ uint32_t As[128 * AS_STRIDE];
    __shared__ uint32_t Bs[32 * BS_STRIDE];
    const int tid = threadIdx.x;
    const int wid = tid >> 5, lane = tid & 31;
    const int warpM = (wid >> 2) * 64;
    const int warpN = (wid & 3) * 32;
    const int brow = blockIdx.x * 128;
    const int bcol = blockIdx.y * 128;
    const int r = lane >> 2;   // 0..7
    const int cq = lane & 3;   // 0..3

    float acc[4][4][4];
#pragma unroll
    for (int mt = 0; mt < 4; mt++)
#pragma unroll
        for (int nt = 0; nt < 4; nt++)
#pragma unroll
            for (int i = 0; i < 4; i++) acc[mt][nt][i] = 0.f;

    const int lm = tid >> 3;          // 0..31 (A row in 32-row group)
    const int lk4 = (tid & 7) * 4;    // A k offset (float4)
    const int ln4 = lane * 4;         // B n offset (float4)

    for (int k0 = 0; k0 < K; k0 += 32) {
        // A tile 128x32 -> As[m][k] (stride 36), tf32-rounded, STS.128
#pragma unroll
        for (int i = 0; i < 4; i++) {
            int m = lm + i * 32;
            int grow = brow + m;
            float4 v = make_float4(0.f, 0.f, 0.f, 0.f);
            if (grow < M) v = *(const float4*)&A[(size_t)grow * lda + k0 + lk4];
            uint4 u = make_uint4(f2tf32(v.x), f2tf32(v.y), f2tf32(v.z), f2tf32(v.w));
            *(uint4*)&As[m * AS_STRIDE + lk4] = u;
        }
        // B tile 32x128 -> Bs[k][n] (stride 136), STS.128
#pragma unroll
        for (int i = 0; i < 4; i++) {
            int kk = wid + i * 8;
            float4 v = *(const float4*)&B[(size_t)(k0 + kk) * ldb + bcol + ln4];
            uint4 u = make_uint4(f2tf32(v.x), f2tf32(v.y), f2tf32(v.z), f2tf32(v.w));
            *(uint4*)&Bs[kk * BS_STRIDE + ln4] = u;
        }
        __syncthreads();
#pragma unroll
        for (int g = 0; g < 4; g++) {  // four k8 groups
            uint32_t af[4][4];
#pragma unroll
            for (int mt = 0; mt < 4; mt++) {
                int mb = warpM + mt * 16;
                const uint32_t* p0 = &As[(mb + r) * AS_STRIDE + g * 8 + cq];
                const uint32_t* p1 = &As[(mb + r + 8) * AS_STRIDE + g * 8 + cq];
                af[mt][0] = p0[0];
                af[mt][1] = p1[0];
                af[mt][2] = p0[4];
                af[mt][3] = p1[4];
            }
            uint32_t bf[4][2];
#pragma unroll
            for (int nt = 0; nt < 4; nt++) {
                int nb = warpN + nt * 8 + r;
                bf[nt][0] = Bs[(g * 8 + cq) * BS_STRIDE + nb];
                bf[nt][1] = Bs[(g * 8 + cq + 4) * BS_STRIDE + nb];
            }
#pragma unroll
            for (int mt = 0; mt < 4; mt++)
#pragma unroll
                for (int nt = 0; nt < 4; nt++)
                    mma_tf32(acc[mt][nt], af[mt], bf[nt]);
        }
        __syncthreads();
    }

    // epilogue: d0=(r,2c) d1=(r,2c+1) d2=(r+8,2c) d3=(r+8,2c+1)
#pragma unroll
    for (int mt = 0; mt < 4; mt++) {
        int row0 = brow + warpM + mt * 16 + r;
        int row1 = row0 + 8;
#pragma unroll
        for (int nt = 0; nt < 4; nt++) {
            int col = bcol + warpN + nt * 8 + 2 * cq;
            float o0 = acc[mt][nt][0], o1 = acc[mt][nt][1];
            float o2 = acc[mt][nt][2], o3 = acc[mt][nt][3];
            if (mode == 1) {
                float b0 = bias[col], b1 = bias[col + 1];
                o0 += b0; o1 += b1; o2 += b0; o3 += b1;
            } else if (mode == 2) {
                float b0 = bias[col], b1 = bias[col + 1];
                o0 += b0; o1 += b1; o2 += b0; o3 += b1;
                o0 = (o0 > 0.f) ? o0 : 0.01f * o0;
                o1 = (o1 > 0.f) ? o1 : 0.01f * o1;
                o2 = (o2 > 0.f) ? o2 : 0.01f * o2;
                o3 = (o3 > 0.f) ? o3 : 0.01f * o3;
                if (row0 < M) {
                    o0 += res[(size_t)row0 * ldc + col];
                    o1 += res[(size_t)row0 * ldc + col + 1];
                }
                if (row1 < M) {
                    o2 += res[(size_t)row1 * ldc + col];
                    o3 += res[(size_t)row1 * ldc + col + 1];
                }
            }
            if (row0 < M) *(float2*)&C[(size_t)row0 * ldc + col] = make_float2(o0, o1);
            if (row1 < M) *(float2*)&C[(size_t)row1 * ldc + col] = make_float2(o2, o3);
        }
    }
}

// ---------------- per-node multi-aggregator reduce -------------------------
__global__ __launch_bounds__(256)
void aggregate_kernel() {
    int gw = (blockIdx.x * blockDim.x + threadIdx.x) >> 5;
    int lane = threadIdx.x & 31;
    if (gw >= NN) return;
    const float4* P4 = (const float4*)g_P;
    const float4* Q4 = (const float4*)g_Q;
    float4 q = Q4[(size_t)gw * 32 + lane];
    int s = g_rowptr[gw], e = g_rowptr[gw + 1];
    float4 sm = make_float4(0.f, 0.f, 0.f, 0.f);
    float4 ss = make_float4(0.f, 0.f, 0.f, 0.f);
    float4 mx = make_float4(-3.4e38f, -3.4e38f, -3.4e38f, -3.4e38f);
    float4 mn = make_float4(3.4e38f, 3.4e38f, 3.4e38f, 3.4e38f);
    for (int i = s; i < e; i++) {
        int src = g_srcs[i];
        float4 p = P4[(size_t)src * 32 + lane];
        float ex = fmaxf(p.x + q.x, 0.f);
        float ey = fmaxf(p.y + q.y, 0.f);
        float ez = fmaxf(p.z + q.z, 0.f);
        float ew = fmaxf(p.w + q.w, 0.f);
        sm.x += ex; sm.y += ey; sm.z += ez; sm.w += ew;
        ss.x += ex * ex; ss.y += ey * ey; ss.z += ez * ez; ss.w += ew * ew;
        mx.x = fmaxf(mx.x, ex); mx.y = fmaxf(mx.y, ey);
        mx.z = fmaxf(mx.z, ez); mx.w = fmaxf(mx.w, ew);
        mn.x = fminf(mn.x, ex); mn.y = fminf(mn.y, ey);
        mn.z = fminf(mn.z, ez); mn.w = fminf(mn.w, ew);
    }
    float deg = (float)(e - s);
    float inv = 1.0f / deg;
    float4 mean = make_float4(sm.x * inv, sm.y * inv, sm.z * inv, sm.w * inv);
    float4 msq  = make_float4(ss.x * inv, ss.y * inv, ss.z * inv, ss.w * inv);
    float4 sd;
    sd.x = sqrtf(fmaxf(msq.x - mean.x * mean.x, 0.f) + 1e-5f);
    sd.y = sqrtf(fmaxf(msq.y - mean.y * mean.y, 0.f) + 1e-5f);
    sd.z = sqrtf(fmaxf(msq.z - mean.z * mean.z, 0.f) + 1e-5f);
    sd.w = sqrtf(fmaxf(msq.w - mean.w * mean.w, 0.f) + 1e-5f);
    float4* out = (float4*)(g_agg + (size_t)gw * 512);
    out[lane]      = mean;
    out[32 + lane] = mx;
    out[64 + lane] = mn;
    out[96 + lane] = sd;
    if (lane == 0) {
        float ld = logf(deg + 1.0f);
        g_sa[gw] = ld * (1.0f / AVG_D_LOG_F);
        g_sb[gw] = AVG_D_LOG_F / ld;
    }
}

// ---------------- combine: hp = relu(H0 + Y0 + a*Y1 + b*Y2 + b_post) -------
__global__ void combine_kernel(const float* __restrict__ b_post) {
    int idx = blockIdx.x * blockDim.x + threadIdx.x;
    if (idx >= NN * 32) return;
    int n = idx >> 5, l = idx & 31;
    const float4* H04 = (const float4*)g_H0;
    const float4* Y4 = (const float4*)g_Y;
    const float4* bp4 = (const float4*)b_post;
    float a = g_sa[n], b = g_sb[n];
    float4 h0 = H04[idx];
    float4 y0 = Y4[(size_t)n * 96 + l];
    float4 y1 = Y4[(size_t)n * 96 + 32 + l];
    float4 y2 = Y4[(size_t)n * 96 + 64 + l];
    float4 bb = bp4[l];
    float4 v;
    v.x = fmaxf(h0.x + y0.x + a * y1.x + b * y2.x + bb.x, 0.f);
    v.y = fmaxf(h0.y + y0.y + a * y1.y + b * y2.y + bb.y, 0.f);
    v.z = fmaxf(h0.z + y0.z + a * y1.z + b * y2.z + bb.z, 0.f);
    v.w = fmaxf(h0.w + y0.w + a * y1.w + b * y2.w + bb.w, 0.f);
    ((float4*)g_hp)[idx] = v;
}

// ---------------- launch ---------------------------------------------------
extern "C" void kernel_launch(void* const* d_in, const int* in_sizes, int n_in,
                              void* d_out, int out_size) {
    const float* h      = (const float*)d_in[0];
    const int*   esrc   = (const int*)d_in[1];
    const int*   edst   = (const int*)d_in[2];
    const float* W_pre  = (const float*)d_in[3];
    const float* b_pre  = (const float*)d_in[4];
    const float* W_post = (const float*)d_in[5];
    const float* b_post = (const float*)d_in[6];
    const float* W_mix  = (const float*)d_in[7];
    const float* b_mix  = (const float*)d_in[8];
    float*       out    = (float*)d_out;

    float *P, *Q, *AGG, *Y, *H0, *HP, *B2;
    cudaGetSymbolAddress((void**)&P,   g_P);
    cudaGetSymbolAddress((void**)&Q,   g_Q);
    cudaGetSymbolAddress((void**)&AGG, g_agg);
    cudaGetSymbolAddress((void**)&Y,   g_Y);
    cudaGetSymbolAddress((void**)&H0,  g_H0);
    cudaGetSymbolAddress((void**)&HP,  g_hp);
    cudaGetSymbolAddress((void**)&B2,  g_B2);

    const int nscan = (NN + 255) / 256;  // 196

    detect_kernel<<<1, 1>>>(edst);
    zero_kernel<<<(NN + 255) / 256, 256>>>();
    hist_kernel<<<(NE + 255) / 256, 256>>>(edst);
    scan1_kernel<<<nscan, 256>>>();
    scan2_kernel<<<1, 256>>>(nscan);
    scan3_kernel<<<nscan, 256>>>();
    scatter_kernel<<<(NE + 255) / 256, 256>>>(edst);
    sortsrc_kernel<<<(NN + 127) / 128, 128>>>(esrc);
    repack_kernel<<<(512 * 384 + 255) / 256, 256>>>(W_post);

    dim3 g1((NN + 127) / 128, 1);
    // P = h @ W_pre[0:128];  Q = h @ W_pre[128:256] + b_pre
    mma_gemm<<<g1, 256>>>(h, 128, W_pre, 128, P, 128, NN, 128, 0, nullptr, nullptr);
    mma_gemm<<<g1, 256>>>(h, 128, W_pre + 128 * 128, 128, Q, 128, NN, 128, 1, b_pre, nullptr);

    aggregate_kernel<<<(NN + 7) / 8, 256>>>();

    // Y = agg @ Bcat  (50000 x 512 x 384)
    dim3 g2((NN + 127) / 128, 3);
    mma_gemm<<<g2, 256>>>(AGG, 512, B2, 384, Y, 384, NN, 512, 0, nullptr, nullptr);
    // H0 = h @ W_post[0:128]
    mma_gemm<<<g1, 256>>>(h, 128, W_post, 128, H0, 128, NN, 128, 0, nullptr, nullptr);

    combine_kernel<<<(NN * 32 + 255) / 256, 256>>>(b_post);

    // out = h + leaky_relu(hp @ W_mix + b_mix)
    mma_gemm<<<g1, 256>>>(HP, 128, W_mix, 128, out, 128, NN, 128, 2, b_mix, h);
}

// round 10
// speedup vs baseline: 2.4679x; 1.1753x over previous
#include <cuda_runtime.h>
#include <math.h>
#include <stdint.h>

#define NN 50000
#define NE 600000
#define AVG_D_LOG_F 1.6094379124341003f  /* log(5) */

// ---------------- scratch (static device arrays; no runtime alloc) --------
__device__ float g_P[NN * 128];          // h @ W_pre[0:128]
__device__ float g_Q[NN * 128];          // h @ W_pre[128:256] + b_pre
__device__ float g_agg[NN * 512];        // [mean, max, min, std] per node
__device__ float g_Y[NN * 384];          // agg @ Bcat
__device__ float g_H0[NN * 128];         // h @ W_post[0:128]
__device__ float g_hp[NN * 128];         // posttrans output
__device__ float g_B2[512 * 384];        // repacked W_post columns
__device__ float g_sa[NN], g_sb[NN];     // per-node scalers
__device__ int   g_cnt[NN], g_cur[NN];
__device__ int   g_rowptr[NN + 1];
__device__ int   g_part[256];
__device__ int   g_eid[NE];
__device__ int   g_srcs[NE];
__device__ int   g_stride;               // 1 if edge arrays int32, 2 if int64

__device__ __forceinline__ uint32_t smem_u32(const void* p) {
    uint32_t a;
    asm("{ .reg .u64 t; cvta.to.shared.u64 t, %1; cvt.u32.u64 %0, t; }"
        : "=r"(a) : "l"(p));
    return a;
}

// ---------------- dtype detection ------------------------------------------
// edge_dst starts with arange(N): int32 reads [0,1,2]; int64 LE reads [0,0,1].
__global__ void detect_kernel(const int* __restrict__ edst32) {
    g_stride = (edst32[1] == 1) ? 1 : 2;
}

// ---------------- CSR build ------------------------------------------------
__global__ void zero_kernel() {
    int i = blockIdx.x * blockDim.x + threadIdx.x;
    if (i < NN) { g_cnt[i] = 0; g_cur[i] = 0; }
}

__global__ void hist_kernel(const int* __restrict__ edst) {
    int i = blockIdx.x * blockDim.x + threadIdx.x;
    if (i < NE) atomicAdd(&g_cnt[edst[(size_t)i * g_stride]], 1);
}

__global__ void scan1_kernel() {
    __shared__ int sh[256];
    int t = threadIdx.x, b = blockIdx.x;
    int i = b * 256 + t;
    sh[t] = (i < NN) ? g_cnt[i] : 0;
    __syncthreads();
    for (int off = 128; off > 0; off >>= 1) {
        if (t < off) sh[t] += sh[t + off];
        __syncthreads();
    }
    if (t == 0) g_part[b] = sh[0];
}

__global__ void scan2_kernel(int nblk) {
    __shared__ int sh[256];
    int t = threadIdx.x;
    int v = (t < nblk) ? g_part[t] : 0;
    sh[t] = v;
    __syncthreads();
    for (int off = 1; off < 256; off <<= 1) {
        int u = (t >= off) ? sh[t - off] : 0;
        __syncthreads();
        sh[t] += u;
        __syncthreads();
    }
    if (t < nblk) g_part[t] = sh[t] - v;
}

__global__ void scan3_kernel() {
    __shared__ int sh[256];
    int t = threadIdx.x, b = blockIdx.x;
    int i = b * 256 + t;
    int c = (i < NN) ? g_cnt[i] : 0;
    sh[t] = c;
    __syncthreads();
    for (int off = 1; off < 256; off <<= 1) {
        int u = (t >= off) ? sh[t - off] : 0;
        __syncthreads();
        sh[t] += u;
        __syncthreads();
    }
    if (i < NN) g_rowptr[i] = g_part[b] + sh[t] - c;
    if (b == 0 && t == 0) g_rowptr[NN] = NE;
}

__global__ void scatter_kernel(const int* __restrict__ edst) {
    int i = blockIdx.x * blockDim.x + threadIdx.x;
    if (i >= NE) return;
    int d = edst[(size_t)i * g_stride];
    int pos = atomicAdd(&g_cur[d], 1);
    g_eid[g_rowptr[d] + pos] = i;
}

__global__ void sortsrc_kernel(const int* __restrict__ esrc) {
    int n = blockIdx.x * blockDim.x + threadIdx.x;
    if (n >= NN) return;
    int st = g_stride;
    int s = g_rowptr[n], e = g_rowptr[n + 1];
    for (int i = s + 1; i < e; i++) {
        int key = g_eid[i];
        int j = i - 1;
        while (j >= s && g_eid[j] > key) { g_eid[j + 1] = g_eid[j]; j--; }
        g_eid[j + 1] = key;
    }
    for (int i = s; i < e; i++) g_srcs[i] = esrc[(size_t)g_eid[i] * st];
}

// ---------------- repack W_post columns into Bcat[512][384] ----------------
__global__ void repack_kernel(const float* __restrict__ W_post) {
    int idx = blockIdx.x * blockDim.x + threadIdx.x;
    if (idx >= 512 * 384) return;
    int k = idx / 384, j = idx % 384;
    int s = j >> 7, jj = j & 127;
    g_B2[idx] = W_post[(size_t)(128 + s * 512 + k) * 128 + jj];
}

// ---------------- tf32 MMA GEMM, 2-stage cp.async pipeline -----------------
// C[M,N] = A[M,K] @ B[K,N]. 128x128x32 tiles, 256 threads (8 warps 2x4),
// warp tile 64x32 via mma.sync.m16n8k8 tf32 (RNA conversion at frag load).
// mode 0: C = acc; 1: C = acc + bias; 2: C = res + leaky_relu(acc + bias)
__device__ __forceinline__ uint32_t f2tf32(float f) {
    uint32_t u;
    asm("cvt.rna.tf32.f32 %0, %1;" : "=r"(u) : "f"(f));
    return u;
}
__device__ __forceinline__ void mma_tf32(float* d, const uint32_t* a,
                                         const uint32_t* b) {
    asm volatile(
        "mma.sync.aligned.m16n8k8.row.col.f32.tf32.tf32.f32 "
        "{%0,%1,%2,%3}, {%4,%5,%6,%7}, {%8,%9}, {%0,%1,%2,%3};"
        : "+f"(d[0]), "+f"(d[1]), "+f"(d[2]), "+f"(d[3])
        : "r"(a[0]), "r"(a[1]), "r"(a[2]), "r"(a[3]), "r"(b[0]), "r"(b[1]));
}

#define ASTR 36    /* As[m][k] padded: conflict-free frag loads, 144B row (16B mult) */
#define BSTR 136   /* Bs[k][n] padded: conflict-free frag loads, 544B row (16B mult) */
#define A_STAGE (128 * ASTR)
#define B_STAGE (32 * BSTR)
#define SMEM_BYTES ((2 * A_STAGE + 2 * B_STAGE) * 4)   /* 71680 */

__global__ __launch_bounds__(256, 2)
void mma_gemm(const float* __restrict__ A, int lda,
              const float* __restrict__ B, int ldb,
              float* __restrict__ C, int ldc,
              int M, int K, int mode,
              const float* __restrict__ bias,
              const float* __restrict__ res) {
    extern __shared__ float sm[];
    float* Asm = sm;                    // 2 stages
    float* Bsm = sm + 2 * A_STAGE;      // 2 stages
    const int tid = threadIdx.x;
    const int wid = tid >> 5, lane = tid & 31;
    const int warpM = (wid >> 2) * 64;
    const int warpN = (wid & 3) * 32;
    const int brow = blockIdx.x * 128;
    const int bcol = blockIdx.y * 128;
    const int r = lane >> 2;   // 0..7
    const int cq = lane & 3;   // 0..3

    float acc[4][4][4];
#pragma unroll
    for (int mt = 0; mt < 4; mt++)
#pragma unroll
        for (int nt = 0; nt < 4; nt++)
#pragma unroll
            for (int i = 0; i < 4; i++) acc[mt][nt][i] = 0.f;

    const int lm = tid >> 3;          // 0..31 (A row in 32-row group)
    const int lk4 = (tid & 7) * 4;    // A k offset (floats)
    const int ln4 = lane * 4;         // B n offset (floats)

    const int nch = K >> 5;

    // async load of chunk ch into stage st
    auto issue = [&](int ch, int st) {
        const int k0 = ch << 5;
        float* as = Asm + st * A_STAGE;
        float* bs = Bsm + st * B_STAGE;
#pragma unroll
        for (int i = 0; i < 4; i++) {
            int m = lm + i * 32;
            int grow = brow + m;
            int cl = (grow < M) ? grow : (M - 1);
            const float* gp = &A[(size_t)cl * lda + k0 + lk4];
            int sz = (grow < M) ? 16 : 0;
            uint32_t sa = smem_u32(&as[m * ASTR + lk4]);
            asm volatile("cp.async.cg.shared.global [%0], [%1], 16, %2;"
                         :: "r"(sa), "l"(gp), "r"(sz));
        }
#pragma unroll
        for (int i = 0; i < 4; i++) {
            int kk = wid + i * 8;
            const float* gp = &B[(size_t)(k0 + kk) * ldb + bcol + ln4];
            uint32_t sa = smem_u32(&bs[kk * BSTR + ln4]);
            asm volatile("cp.async.cg.shared.global [%0], [%1], 16;"
                         :: "r"(sa), "l"(gp));
        }
        asm volatile("cp.async.commit_group;");
    };

    issue(0, 0);
    for (int ch = 0; ch < nch; ch++) {
        if (ch + 1 < nch) {
            issue(ch + 1, (ch + 1) & 1);
            asm volatile("cp.async.wait_group 1;");
        } else {
            asm volatile("cp.async.wait_group 0;");
        }
        __syncthreads();
        const float* as = Asm + (ch & 1) * A_STAGE;
        const float* bs = Bsm + (ch & 1) * B_STAGE;
#pragma unroll
        for (int g = 0; g < 4; g++) {
            uint32_t af[4][4];
#pragma unroll
            for (int mt = 0; mt < 4; mt++) {
                const float* p0 = &as[(warpM + mt * 16 + r) * ASTR + g * 8 + cq];
                const float* p1 = p0 + 8 * ASTR;
                af[mt][0] = f2tf32(p0[0]);
                af[mt][1] = f2tf32(p1[0]);
                af[mt][2] = f2tf32(p0[4]);
                af[mt][3] = f2tf32(p1[4]);
            }
            uint32_t bf[4][2];
#pragma unroll
            for (int nt = 0; nt < 4; nt++) {
                int nb = warpN + nt * 8 + r;
                bf[nt][0] = f2tf32(bs[(g * 8 + cq) * BSTR + nb]);
                bf[nt][1] = f2tf32(bs[(g * 8 + cq + 4) * BSTR + nb]);
            }
#pragma unroll
            for (int mt = 0; mt < 4; mt++)
#pragma unroll
                for (int nt = 0; nt < 4; nt++)
                    mma_tf32(acc[mt][nt], af[mt], bf[nt]);
        }
        __syncthreads();
    }

    // epilogue: d0=(r,2c) d1=(r,2c+1) d2=(r+8,2c) d3=(r+8,2c+1)
#pragma unroll
    for (int mt = 0; mt < 4; mt++) {
        int row0 = brow + warpM + mt * 16 + r;
        int row1 = row0 + 8;
#pragma unroll
        for (int nt = 0; nt < 4; nt++) {
            int col = bcol + warpN + nt * 8 + 2 * cq;
            float o0 = acc[mt][nt][0], o1 = acc[mt][nt][1];
            float o2 = acc[mt][nt][2], o3 = acc[mt][nt][3];
            if (mode == 1) {
                float b0 = bias[col], b1 = bias[col + 1];
                o0 += b0; o1 += b1; o2 += b0; o3 += b1;
            } else if (mode == 2) {
                float b0 = bias[col], b1 = bias[col + 1];
                o0 += b0; o1 += b1; o2 += b0; o3 += b1;
                o0 = (o0 > 0.f) ? o0 : 0.01f * o0;
                o1 = (o1 > 0.f) ? o1 : 0.01f * o1;
                o2 = (o2 > 0.f) ? o2 : 0.01f * o2;
                o3 = (o3 > 0.f) ? o3 : 0.01f * o3;
                if (row0 < M) {
                    o0 += res[(size_t)row0 * ldc + col];
                    o1 += res[(size_t)row0 * ldc + col + 1];
                }
                if (row1 < M) {
                    o2 += res[(size_t)row1 * ldc + col];
                    o3 += res[(size_t)row1 * ldc + col + 1];
                }
            }
            if (row0 < M) *(float2*)&C[(size_t)row0 * ldc + col] = make_float2(o0, o1);
            if (row1 < M) *(float2*)&C[(size_t)row1 * ldc + col] = make_float2(o2, o3);
        }
    }
}

// ---------------- per-node multi-aggregator reduce -------------------------
__global__ __launch_bounds__(256)
void aggregate_kernel() {
    int gw = (blockIdx.x * blockDim.x + threadIdx.x) >> 5;
    int lane = threadIdx.x & 31;
    if (gw >= NN) return;
    const float4* P4 = (const float4*)g_P;
    const float4* Q4 = (const float4*)g_Q;
    float4 q = Q4[(size_t)gw * 32 + lane];
    int s = g_rowptr[gw], e = g_rowptr[gw + 1];
    float4 sm = make_float4(0.f, 0.f, 0.f, 0.f);
    float4 ss = make_float4(0.f, 0.f, 0.f, 0.f);
    float4 mx = make_float4(-3.4e38f, -3.4e38f, -3.4e38f, -3.4e38f);
    float4 mn = make_float4(3.4e38f, 3.4e38f, 3.4e38f, 3.4e38f);
    for (int i = s; i < e; i++) {
        int src = g_srcs[i];
        float4 p = P4[(size_t)src * 32 + lane];
        float ex = fmaxf(p.x + q.x, 0.f);
        float ey = fmaxf(p.y + q.y, 0.f);
        float ez = fmaxf(p.z + q.z, 0.f);
        float ew = fmaxf(p.w + q.w, 0.f);
        sm.x += ex; sm.y += ey; sm.z += ez; sm.w += ew;
        ss.x += ex * ex; ss.y += ey * ey; ss.z += ez * ez; ss.w += ew * ew;
        mx.x = fmaxf(mx.x, ex); mx.y = fmaxf(mx.y, ey);
        mx.z = fmaxf(mx.z, ez); mx.w = fmaxf(mx.w, ew);
        mn.x = fminf(mn.x, ex); mn.y = fminf(mn.y, ey);
        mn.z = fminf(mn.z, ez); mn.w = fminf(mn.w, ew);
    }
    float deg = (float)(e - s);
    float inv = 1.0f / deg;
    float4 mean = make_float4(sm.x * inv, sm.y * inv, sm.z * inv, sm.w * inv);
    float4 msq  = make_float4(ss.x * inv, ss.y * inv, ss.z * inv, ss.w * inv);
    float4 sd;
    sd.x = sqrtf(fmaxf(msq.x - mean.x * mean.x, 0.f) + 1e-5f);
    sd.y = sqrtf(fmaxf(msq.y - mean.y * mean.y, 0.f) + 1e-5f);
    sd.z = sqrtf(fmaxf(msq.z - mean.z * mean.z, 0.f) + 1e-5f);
    sd.w = sqrtf(fmaxf(msq.w - mean.w * mean.w, 0.f) + 1e-5f);
    float4* out = (float4*)(g_agg + (size_t)gw * 512);
    out[lane]      = mean;
    out[32 + lane] = mx;
    out[64 + lane] = mn;
    out[96 + lane] = sd;
    if (lane == 0) {
        float ld = logf(deg + 1.0f);
        g_sa[gw] = ld * (1.0f / AVG_D_LOG_F);
        g_sb[gw] = AVG_D_LOG_F / ld;
    }
}

// ---------------- combine: hp = relu(H0 + Y0 + a*Y1 + b*Y2 + b_post) -------
__global__ void combine_kernel(const float* __restrict__ b_post) {
    int idx = blockIdx.x * blockDim.x + threadIdx.x;
    if (idx >= NN * 32) return;
    int n = idx >> 5, l = idx & 31;
    const float4* H04 = (const float4*)g_H0;
    const float4* Y4 = (const float4*)g_Y;
    const float4* bp4 = (const float4*)b_post;
    float a = g_sa[n], b = g_sb[n];
    float4 h0 = H04[idx];
    float4 y0 = Y4[(size_t)n * 96 + l];
    float4 y1 = Y4[(size_t)n * 96 + 32 + l];
    float4 y2 = Y4[(size_t)n * 96 + 64 + l];
    float4 bb = bp4[l];
    float4 v;
    v.x = fmaxf(h0.x + y0.x + a * y1.x + b * y2.x + bb.x, 0.f);
    v.y = fmaxf(h0.y + y0.y + a * y1.y + b * y2.y + bb.y, 0.f);
    v.z = fmaxf(h0.z + y0.z + a * y1.z + b * y2.z + bb.z, 0.f);
    v.w = fmaxf(h0.w + y0.w + a * y1.w + b * y2.w + bb.w, 0.f);
    ((float4*)g_hp)[idx] = v;
}

// ---------------- launch ---------------------------------------------------
extern "C" void kernel_launch(void* const* d_in, const int* in_sizes, int n_in,
                              void* d_out, int out_size) {
    const float* h      = (const float*)d_in[0];
    const int*   esrc   = (const int*)d_in[1];
    const int*   edst   = (const int*)d_in[2];
    const float* W_pre  = (const float*)d_in[3];
    const float* b_pre  = (const float*)d_in[4];
    const float* W_post = (const float*)d_in[5];
    const float* b_post = (const float*)d_in[6];
    const float* W_mix  = (const float*)d_in[7];
    const float* b_mix  = (const float*)d_in[8];
    float*       out    = (float*)d_out;

    float *P, *Q, *AGG, *Y, *H0, *HP, *B2;
    cudaGetSymbolAddress((void**)&P,   g_P);
    cudaGetSymbolAddress((void**)&Q,   g_Q);
    cudaGetSymbolAddress((void**)&AGG, g_agg);
    cudaGetSymbolAddress((void**)&Y,   g_Y);
    cudaGetSymbolAddress((void**)&H0,  g_H0);
    cudaGetSymbolAddress((void**)&HP,  g_hp);
    cudaGetSymbolAddress((void**)&B2,  g_B2);

    cudaFuncSetAttribute(mma_gemm, cudaFuncAttributeMaxDynamicSharedMemorySize,
                         SMEM_BYTES);

    const int nscan = (NN + 255) / 256;  // 196

    detect_kernel<<<1, 1>>>(edst);
    zero_kernel<<<(NN + 255) / 256, 256>>>();
    hist_kernel<<<(NE + 255) / 256, 256>>>(edst);
    scan1_kernel<<<nscan, 256>>>();
    scan2_kernel<<<1, 256>>>(nscan);
    scan3_kernel<<<nscan, 256>>>();
    scatter_kernel<<<(NE + 255) / 256, 256>>>(edst);
    sortsrc_kernel<<<(NN + 127) / 128, 128>>>(esrc);
    repack_kernel<<<(512 * 384 + 255) / 256, 256>>>(W_post);

    dim3 g1((NN + 127) / 128, 1);
    // P = h @ W_pre[0:128];  Q = h @ W_pre[128:256] + b_pre
    mma_gemm<<<g1, 256, SMEM_BYTES>>>(h, 128, W_pre, 128, P, 128, NN, 128, 0,
                                      nullptr, nullptr);
    mma_gemm<<<g1, 256, SMEM_BYTES>>>(h, 128, W_pre + 128 * 128, 128, Q, 128,
                                      NN, 128, 1, b_pre, nullptr);

    aggregate_kernel<<<(NN + 7) / 8, 256>>>();

    // Y = agg @ Bcat  (50000 x 512 x 384)
    dim3 g2((NN + 127) / 128, 3);
    mma_gemm<<<g2, 256, SMEM_BYTES>>>(AGG, 512, B2, 384, Y, 384, NN, 512, 0,
                                      nullptr, nullptr);
    // H0 = h @ W_post[0:128]
    mma_gemm<<<g1, 256, SMEM_BYTES>>>(h, 128, W_post, 128, H0, 128, NN, 128, 0,
                                      nullptr, nullptr);

    combine_kernel<<<(NN * 32 + 255) / 256, 256>>>(b_post);

    // out = h + leaky_relu(hp @ W_mix + b_mix)
    mma_gemm<<<g1, 256, SMEM_BYTES>>>(HP, 128, W_mix, 128, out, 128, NN, 128, 2,
                                      b_mix, h);
}

// round 11
// speedup vs baseline: 2.5516x; 1.0339x over previous
#include <cuda_runtime.h>
#include <math.h>
#include <stdint.h>

#define NN 50000
#define NE 600000
#define AVG_D_LOG_F 1.6094379124341003f  /* log(5) */

// ---------------- scratch (static device arrays; no runtime alloc) --------
__device__ float g_P[NN * 128];          // h @ W_pre[0:128]
__device__ float g_Q[NN * 128];          // h @ W_pre[128:256] + b_pre
__device__ float g_agg[NN * 512];        // [mean, max, min, std] per node
__device__ float g_Y[NN * 384];          // agg @ Bcat
__device__ float g_H0[NN * 128];         // h @ W_post[0:128]
__device__ float g_hp[NN * 128];         // posttrans output
__device__ float g_B2[512 * 384];        // repacked W_post columns
__device__ float g_sa[NN], g_sb[NN];     // per-node scalers
__device__ int   g_cnt[NN], g_cur[NN];
__device__ int   g_rowptr[NN + 1];
__device__ int   g_part[256];
__device__ int   g_eid[NE];
__device__ int   g_srcs[NE];
__device__ int   g_stride;               // 1 if edge arrays int32, 2 if int64

__device__ __forceinline__ uint32_t smem_u32(const void* p) {
    uint32_t a;
    asm("{ .reg .u64 t; cvta.to.shared.u64 t, %1; cvt.u32.u64 %0, t; }"
        : "=r"(a) : "l"(p));
    return a;
}

// ---------------- dtype detect + zero (fused) -------------------------------
// edge_dst starts with arange(N): int32 reads [0,1,2]; int64 LE reads [0,0,1].
__global__ void zero_detect_kernel(const int* __restrict__ edst32) {
    int i = blockIdx.x * blockDim.x + threadIdx.x;
    if (i < NN) { g_cnt[i] = 0; g_cur[i] = 0; }
    if (i == 0) g_stride = (edst32[1] == 1) ? 1 : 2;
}

// ---------------- CSR build ------------------------------------------------
__global__ void hist_kernel(const int* __restrict__ edst) {
    int i = blockIdx.x * blockDim.x + threadIdx.x;
    if (i < NE) atomicAdd(&g_cnt[edst[(size_t)i * g_stride]], 1);
}

__global__ void scan1_kernel() {
    __shared__ int sh[256];
    int t = threadIdx.x, b = blockIdx.x;
    int i = b * 256 + t;
    sh[t] = (i < NN) ? g_cnt[i] : 0;
    __syncthreads();
    for (int off = 128; off > 0; off >>= 1) {
        if (t < off) sh[t] += sh[t + off];
        __syncthreads();
    }
    if (t == 0) g_part[b] = sh[0];
}

__global__ void scan2_kernel(int nblk) {
    __shared__ int sh[256];
    int t = threadIdx.x;
    int v = (t < nblk) ? g_part[t] : 0;
    sh[t] = v;
    __syncthreads();
    for (int off = 1; off < 256; off <<= 1) {
        int u = (t >= off) ? sh[t - off] : 0;
        __syncthreads();
        sh[t] += u;
        __syncthreads();
    }
    if (t < nblk) g_part[t] = sh[t] - v;
}

__global__ void scan3_kernel() {
    __shared__ int sh[256];
    int t = threadIdx.x, b = blockIdx.x;
    int i = b * 256 + t;
    int c = (i < NN) ? g_cnt[i] : 0;
    sh[t] = c;
    __syncthreads();
    for (int off = 1; off < 256; off <<= 1) {
        int u = (t >= off) ? sh[t - off] : 0;
        __syncthreads();
        sh[t] += u;
        __syncthreads();
    }
    if (i < NN) g_rowptr[i] = g_part[b] + sh[t] - c;
    if (b == 0 && t == 0) g_rowptr[NN] = NE;
}

__global__ void scatter_kernel(const int* __restrict__ edst) {
    int i = blockIdx.x * blockDim.x + threadIdx.x;
    if (i >= NE) return;
    int d = edst[(size_t)i * g_stride];
    int pos = atomicAdd(&g_cur[d], 1);
    g_eid[g_rowptr[d] + pos] = i;
}

__global__ void sortsrc_kernel(const int* __restrict__ esrc) {
    int n = blockIdx.x * blockDim.x + threadIdx.x;
    if (n >= NN) return;
    int st = g_stride;
    int s = g_rowptr[n], e = g_rowptr[n + 1];
    for (int i = s + 1; i < e; i++) {
        int key = g_eid[i];
        int j = i - 1;
        while (j >= s && g_eid[j] > key) { g_eid[j + 1] = g_eid[j]; j--; }
        g_eid[j + 1] = key;
    }
    for (int i = s; i < e; i++) g_srcs[i] = esrc[(size_t)g_eid[i] * st];
}

// ---------------- repack W_post columns into Bcat[512][384] ----------------
__global__ void repack_kernel(const float* __restrict__ W_post) {
    int idx = blockIdx.x * blockDim.x + threadIdx.x;
    if (idx >= 512 * 384) return;
    int k = idx / 384, j = idx % 384;
    int s = j >> 7, jj = j & 127;
    g_B2[idx] = W_post[(size_t)(128 + s * 512 + k) * 128 + jj];
}

// ---------------- tf32 MMA GEMM core, 2-stage cp.async pipeline ------------
// C[M,N] = A[M,K] @ B[K,N]. 128x128x32 tiles, 256 threads (8 warps 2x4),
// warp tile 64x32 via mma.sync.m16n8k8 tf32 (RNA conversion at frag load).
// mode 0: C = acc; 1: C = acc + bias; 2: C = res + leaky_relu(acc + bias)
__device__ __forceinline__ uint32_t f2tf32(float f) {
    uint32_t u;
    asm("cvt.rna.tf32.f32 %0, %1;" : "=r"(u) : "f"(f));
    return u;
}
__device__ __forceinline__ void mma_tf32(float* d, const uint32_t* a,
                                         const uint32_t* b) {
    asm volatile(
        "mma.sync.aligned.m16n8k8.row.col.f32.tf32.tf32.f32 "
        "{%0,%1,%2,%3}, {%4,%5,%6,%7}, {%8,%9}, {%0,%1,%2,%3};"
        : "+f"(d[0]), "+f"(d[1]), "+f"(d[2]), "+f"(d[3])
        : "r"(a[0]), "r"(a[1]), "r"(a[2]), "r"(a[3]), "r"(b[0]), "r"(b[1]));
}

#define ASTR 36
#define BSTR 136
#define A_STAGE (128 * ASTR)
#define B_STAGE (32 * BSTR)
#define SMEM_BYTES ((2 * A_STAGE + 2 * B_STAGE) * 4)   /* 71680 */

__device__ __forceinline__
void gemm_core(const float* __restrict__ A, int lda,
               const float* __restrict__ B, int ldb,
               float* __restrict__ C, int ldc,
               int M, int K, int mode,
               const float* __restrict__ bias,
               const float* __restrict__ res,
               int brow, int bcol, float* sm) {
    float* Asm = sm;
    float* Bsm = sm + 2 * A_STAGE;
    const int tid = threadIdx.x;
    const int wid = tid >> 5, lane = tid & 31;
    const int warpM = (wid >> 2) * 64;
    const int warpN = (wid & 3) * 32;
    const int r = lane >> 2;
    const int cq = lane & 3;

    float acc[4][4][4];
#pragma unroll
    for (int mt = 0; mt < 4; mt++)
#pragma unroll
        for (int nt = 0; nt < 4; nt++)
#pragma unroll
            for (int i = 0; i < 4; i++) acc[mt][nt][i] = 0.f;

    const int lm = tid >> 3;
    const int lk4 = (tid & 7) * 4;
    const int ln4 = lane * 4;
    const int nch = K >> 5;

    auto issue = [&](int ch, int st) {
        const int k0 = ch << 5;
        float* as = Asm + st * A_STAGE;
        float* bs = Bsm + st * B_STAGE;
#pragma unroll
        for (int i = 0; i < 4; i++) {
            int m = lm + i * 32;
            int grow = brow + m;
            int cl = (grow < M) ? grow : (M - 1);
            const float* gp = &A[(size_t)cl * lda + k0 + lk4];
            int sz = (grow < M) ? 16 : 0;
            uint32_t sa = smem_u32(&as[m * ASTR + lk4]);
            asm volatile("cp.async.cg.shared.global [%0], [%1], 16, %2;"
                         :: "r"(sa), "l"(gp), "r"(sz));
        }
#pragma unroll
        for (int i = 0; i < 4; i++) {
            int kk = wid + i * 8;
            const float* gp = &B[(size_t)(k0 + kk) * ldb + bcol + ln4];
            uint32_t sa = smem_u32(&bs[kk * BSTR + ln4]);
            asm volatile("cp.async.cg.shared.global [%0], [%1], 16;"
                         :: "r"(sa), "l"(gp));
        }
        asm volatile("cp.async.commit_group;");
    };

    issue(0, 0);
    for (int ch = 0; ch < nch; ch++) {
        if (ch + 1 < nch) {
            issue(ch + 1, (ch + 1) & 1);
            asm volatile("cp.async.wait_group 1;");
        } else {
            asm volatile("cp.async.wait_group 0;");
        }
        __syncthreads();
        const float* as = Asm + (ch & 1) * A_STAGE;
        const float* bs = Bsm + (ch & 1) * B_STAGE;
#pragma unroll
        for (int g = 0; g < 4; g++) {
            uint32_t af[4][4];
#pragma unroll
            for (int mt = 0; mt < 4; mt++) {
                const float* p0 = &as[(warpM + mt * 16 + r) * ASTR + g * 8 + cq];
                const float* p1 = p0 + 8 * ASTR;
                af[mt][0] = f2tf32(p0[0]);
                af[mt][1] = f2tf32(p1[0]);
                af[mt][2] = f2tf32(p0[4]);
                af[mt][3] = f2tf32(p1[4]);
            }
            uint32_t bf[4][2];
#pragma unroll
            for (int nt = 0; nt < 4; nt++) {
                int nb = warpN + nt * 8 + r;
                bf[nt][0] = f2tf32(bs[(g * 8 + cq) * BSTR + nb]);
                bf[nt][1] = f2tf32(bs[(g * 8 + cq + 4) * BSTR + nb]);
            }
#pragma unroll
            for (int mt = 0; mt < 4; mt++)
#pragma unroll
                for (int nt = 0; nt < 4; nt++)
                    mma_tf32(acc[mt][nt], af[mt], bf[nt]);
        }
        __syncthreads();
    }

#pragma unroll
    for (int mt = 0; mt < 4; mt++) {
        int row0 = brow + warpM + mt * 16 + r;
        int row1 = row0 + 8;
#pragma unroll
        for (int nt = 0; nt < 4; nt++) {
            int col = bcol + warpN + nt * 8 + 2 * cq;
            float o0 = acc[mt][nt][0], o1 = acc[mt][nt][1];
            float o2 = acc[mt][nt][2], o3 = acc[mt][nt][3];
            if (mode == 1) {
                float b0 = bias[col], b1 = bias[col + 1];
                o0 += b0; o1 += b1; o2 += b0; o3 += b1;
            } else if (mode == 2) {
                float b0 = bias[col], b1 = bias[col + 1];
                o0 += b0; o1 += b1; o2 += b0; o3 += b1;
                o0 = (o0 > 0.f) ? o0 : 0.01f * o0;
                o1 = (o1 > 0.f) ? o1 : 0.01f * o1;
                o2 = (o2 > 0.f) ? o2 : 0.01f * o2;
                o3 = (o3 > 0.f) ? o3 : 0.01f * o3;
                if (row0 < M) {
                    o0 += res[(size_t)row0 * ldc + col];
                    o1 += res[(size_t)row0 * ldc + col + 1];
                }
                if (row1 < M) {
                    o2 += res[(size_t)row1 * ldc + col];
                    o3 += res[(size_t)row1 * ldc + col + 1];
                }
            }
            if (row0 < M) *(float2*)&C[(size_t)row0 * ldc + col] = make_float2(o0, o1);
            if (row1 < M) *(float2*)&C[(size_t)row1 * ldc + col] = make_float2(o2, o3);
        }
    }
}

// generic wrapper (Y GEMM, H0 GEMM, final GEMM)
__global__ __launch_bounds__(256, 2)
void mma_gemm(const float* __restrict__ A, int lda,
              const float* __restrict__ B, int ldb,
              float* __restrict__ C, int ldc,
              int M, int K, int mode,
              const float* __restrict__ bias,
              const float* __restrict__ res) {
    extern __shared__ float sm[];
    gemm_core(A, lda, B, ldb, C, ldc, M, K, mode, bias, res,
              blockIdx.x * 128, blockIdx.y * 128, sm);
}

// merged P/Q wrapper: grid.y==0 -> P (no bias), grid.y==1 -> Q (+b_pre)
__global__ __launch_bounds__(256, 2)
void mma_gemm_pq(const float* __restrict__ h,
                 const float* __restrict__ W_pre,
                 const float* __restrict__ b_pre,
                 float* __restrict__ P, float* __restrict__ Q) {
    extern __shared__ float sm[];
    int y = blockIdx.y;
    const float* B = W_pre + (size_t)y * 128 * 128;
    float* C = y ? Q : P;
    gemm_core(h, 128, B, 128, C, 128, NN, 128, y, b_pre, nullptr,
              blockIdx.x * 128, 0, sm);
}

// ---------------- per-node multi-aggregator reduce -------------------------
__global__ __launch_bounds__(256)
void aggregate_kernel() {
    int gw = (blockIdx.x * blockDim.x + threadIdx.x) >> 5;
    int lane = threadIdx.x & 31;
    if (gw >= NN) return;
    const float4* P4 = (const float4*)g_P;
    const float4* Q4 = (const float4*)g_Q;
    float4 q = Q4[(size_t)gw * 32 + lane];
    int s = g_rowptr[gw], e = g_rowptr[gw + 1];
    float4 sm = make_float4(0.f, 0.f, 0.f, 0.f);
    float4 ss = make_float4(0.f, 0.f, 0.f, 0.f);
    float4 mx = make_float4(-3.4e38f, -3.4e38f, -3.4e38f, -3.4e38f);
    float4 mn = make_float4(3.4e38f, 3.4e38f, 3.4e38f, 3.4e38f);
    for (int i = s; i < e; i++) {
        int src = g_srcs[i];
        float4 p = P4[(size_t)src * 32 + lane];
        float ex = fmaxf(p.x + q.x, 0.f);
        float ey = fmaxf(p.y + q.y, 0.f);
        float ez = fmaxf(p.z + q.z, 0.f);
        float ew = fmaxf(p.w + q.w, 0.f);
        sm.x += ex; sm.y += ey; sm.z += ez; sm.w += ew;
        ss.x += ex * ex; ss.y += ey * ey; ss.z += ez * ez; ss.w += ew * ew;
        mx.x = fmaxf(mx.x, ex); mx.y = fmaxf(mx.y, ey);
        mx.z = fmaxf(mx.z, ez); mx.w = fmaxf(mx.w, ew);
        mn.x = fminf(mn.x, ex); mn.y = fminf(mn.y, ey);
        mn.z = fminf(mn.z, ez); mn.w = fminf(mn.w, ew);
    }
    float deg = (float)(e - s);
    float inv = 1.0f / deg;
    float4 mean = make_float4(sm.x * inv, sm.y * inv, sm.z * inv, sm.w * inv);
    float4 msq  = make_float4(ss.x * inv, ss.y * inv, ss.z * inv, ss.w * inv);
    float4 sd;
    sd.x = sqrtf(fmaxf(msq.x - mean.x * mean.x, 0.f) + 1e-5f);
    sd.y = sqrtf(fmaxf(msq.y - mean.y * mean.y, 0.f) + 1e-5f);
    sd.z = sqrtf(fmaxf(msq.z - mean.z * mean.z, 0.f) + 1e-5f);
    sd.w = sqrtf(fmaxf(msq.w - mean.w * mean.w, 0.f) + 1e-5f);
    float4* out = (float4*)(g_agg + (size_t)gw * 512);
    out[lane]      = mean;
    out[32 + lane] = mx;
    out[64 + lane] = mn;
    out[96 + lane] = sd;
    if (lane == 0) {
        float ld = logf(deg + 1.0f);
        g_sa[gw] = ld * (1.0f / AVG_D_LOG_F);
        g_sb[gw] = AVG_D_LOG_F / ld;
    }
}

// ---------------- combine: hp = relu(H0 + Y0 + a*Y1 + b*Y2 + b_post) -------
__global__ void combine_kernel(const float* __restrict__ b_post) {
    int idx = blockIdx.x * blockDim.x + threadIdx.x;
    if (idx >= NN * 32) return;
    int n = idx >> 5, l = idx & 31;
    const float4* H04 = (const float4*)g_H0;
    const float4* Y4 = (const float4*)g_Y;
    const float4* bp4 = (const float4*)b_post;
    float a = g_sa[n], b = g_sb[n];
    float4 h0 = H04[idx];
    float4 y0 = Y4[(size_t)n * 96 + l];
    float4 y1 = Y4[(size_t)n * 96 + 32 + l];
    float4 y2 = Y4[(size_t)n * 96 + 64 + l];
    float4 bb = bp4[l];
    float4 v;
    v.x = fmaxf(h0.x + y0.x + a * y1.x + b * y2.x + bb.x, 0.f);
    v.y = fmaxf(h0.y + y0.y + a * y1.y + b * y2.y + bb.y, 0.f);
    v.z = fmaxf(h0.z + y0.z + a * y1.z + b * y2.z + bb.z, 0.f);
    v.w = fmaxf(h0.w + y0.w + a * y1.w + b * y2.w + bb.w, 0.f);
    ((float4*)g_hp)[idx] = v;
}

// ---------------- launch ---------------------------------------------------
extern "C" void kernel_launch(void* const* d_in, const int* in_sizes, int n_in,
                              void* d_out, int out_size) {
    const float* h      = (const float*)d_in[0];
    const int*   esrc   = (const int*)d_in[1];
    const int*   edst   = (const int*)d_in[2];
    const float* W_pre  = (const float*)d_in[3];
    const float* b_pre  = (const float*)d_in[4];
    const float* W_post = (const float*)d_in[5];
    const float* b_post = (const float*)d_in[6];
    const float* W_mix  = (const float*)d_in[7];
    const float* b_mix  = (const float*)d_in[8];
    float*       out    = (float*)d_out;

    float *P, *Q, *AGG, *Y, *H0, *HP, *B2;
    cudaGetSymbolAddress((void**)&P,   g_P);
    cudaGetSymbolAddress((void**)&Q,   g_Q);
    cudaGetSymbolAddress((void**)&AGG, g_agg);
    cudaGetSymbolAddress((void**)&Y,   g_Y);
    cudaGetSymbolAddress((void**)&H0,  g_H0);
    cudaGetSymbolAddress((void**)&HP,  g_hp);
    cudaGetSymbolAddress((void**)&B2,  g_B2);

    cudaFuncSetAttribute(mma_gemm, cudaFuncAttributeMaxDynamicSharedMemorySize,
                         SMEM_BYTES);
    cudaFuncSetAttribute(mma_gemm_pq, cudaFuncAttributeMaxDynamicSharedMemorySize,
                         SMEM_BYTES);

    // Side stream + events: created once (before first capture), reused.
    // Every call enqueues the identical work graph.
    static cudaStream_t s2 = nullptr;
    static cudaEvent_t evFork = nullptr, evCsr = nullptr, evH0 = nullptr;
    if (s2 == nullptr) {
        cudaStreamCreateWithFlags(&s2, cudaStreamNonBlocking);
        cudaEventCreateWithFlags(&evFork, cudaEventDisableTiming);
        cudaEventCreateWithFlags(&evCsr, cudaEventDisableTiming);
        cudaEventCreateWithFlags(&evH0, cudaEventDisableTiming);
    }

    const int nscan = (NN + 255) / 256;  // 196
    dim3 g1((NN + 127) / 128, 1);

    // ---- fork: side stream runs CSR chain + repack, then H0 GEMM ----
    cudaEventRecord(evFork, 0);
    cudaStreamWaitEvent(s2, evFork, 0);

    zero_detect_kernel<<<(NN + 255) / 256, 256, 0, s2>>>(edst);
    hist_kernel<<<(NE + 255) / 256, 256, 0, s2>>>(edst);
    scan1_kernel<<<nscan, 256, 0, s2>>>();
    scan2_kernel<<<1, 256, 0, s2>>>(nscan);
    scan3_kernel<<<nscan, 256, 0, s2>>>();
    scatter_kernel<<<(NE + 255) / 256, 256, 0, s2>>>(edst);
    sortsrc_kernel<<<(NN + 127) / 128, 128, 0, s2>>>(esrc);
    repack_kernel<<<(512 * 384 + 255) / 256, 256, 0, s2>>>(W_post);
    cudaEventRecord(evCsr, s2);

    // H0 = h @ W_post[0:128]  (only needed at combine) — stays on s2
    mma_gemm<<<g1, 256, SMEM_BYTES, s2>>>(h, 128, W_post, 128, H0, 128,
                                          NN, 128, 0, nullptr, nullptr);
    cudaEventRecord(evH0, s2);

    // ---- main stream: P,Q merged GEMM ----
    dim3 gpq((NN + 127) / 128, 2);
    mma_gemm_pq<<<gpq, 256, SMEM_BYTES>>>(h, W_pre, b_pre, P, Q);

    // join CSR, then aggregate
    cudaStreamWaitEvent(0, evCsr, 0);
    aggregate_kernel<<<(NN + 7) / 8, 256>>>();

    // Y = agg @ Bcat  (50000 x 512 x 384)
    dim3 g2((NN + 127) / 128, 3);
    mma_gemm<<<g2, 256, SMEM_BYTES>>>(AGG, 512, B2, 384, Y, 384, NN, 512, 0,
                                      nullptr, nullptr);

    // join H0, then combine + final GEMM
    cudaStreamWaitEvent(0, evH0, 0);
    combine_kernel<<<(NN * 32 + 255) / 256, 256>>>(b_post);
    mma_gemm<<<g1, 256, SMEM_BYTES>>>(HP, 128, W_mix, 128, out, 128, NN, 128, 2,
                                      b_mix, h);
}

// round 12
// speedup vs baseline: 2.5605x; 1.0035x over previous
#include <cuda_runtime.h>
#include <math.h>
#include <stdint.h>

#define NN 50000
#define NE 600000
#define AVG_D_LOG_F 1.6094379124341003f  /* log(5) */

// ---------------- scratch (static device arrays; no runtime alloc) --------
__device__ float g_P[NN * 128];          // h @ W_pre[0:128]
__device__ float g_Q[NN * 128];          // h @ W_pre[128:256] + b_pre
__device__ float g_agg[NN * 512];        // [mean, max, min, std], tf32-rounded
__device__ float g_Y[NN * 384];          // agg @ Bcat
__device__ float g_H0[NN * 128];         // h @ W_post[0:128]
__device__ float g_hp[NN * 128];         // posttrans output, tf32-rounded
__device__ float g_hr[NN * 128];         // h, tf32-rounded (GEMM A operand)
__device__ float g_B2[512 * 384];        // repacked W_post cols, tf32-rounded
__device__ float g_Wr[4 * 16384];        // [W_pre0, W_pre1, W_post0, W_mix], rounded
__device__ float g_sa[NN], g_sb[NN];     // per-node scalers
__device__ int   g_cnt[NN], g_cur[NN];
__device__ int   g_rowptr[NN + 1];
__device__ int   g_part[256];
__device__ int   g_eid[NE];
__device__ int   g_srcs[NE];
__device__ int   g_stride;               // 1 if edge arrays int32, 2 if int64

__device__ __forceinline__ uint32_t smem_u32(const void* p) {
    uint32_t a;
    asm("{ .reg .u64 t; cvta.to.shared.u64 t, %1; cvt.u32.u64 %0, t; }"
        : "=r"(a) : "l"(p));
    return a;
}
__device__ __forceinline__ float rnd_tf32(float f) {
    uint32_t u;
    asm("cvt.rna.tf32.f32 %0, %1;" : "=r"(u) : "f"(f));
    return __uint_as_float(u);
}

// ---------------- dtype detect + zero (fused) -------------------------------
// edge_dst starts with arange(N): int32 reads [0,1,2]; int64 LE reads [0,0,1].
__global__ void zero_detect_kernel(const int* __restrict__ edst32) {
    int i = blockIdx.x * blockDim.x + threadIdx.x;
    if (i < NN) { g_cnt[i] = 0; g_cur[i] = 0; }
    if (i == 0) g_stride = (edst32[1] == 1) ? 1 : 2;
}

// ---------------- CSR build ------------------------------------------------
__global__ void hist_kernel(const int* __restrict__ edst) {
    int i = blockIdx.x * blockDim.x + threadIdx.x;
    if (i < NE) atomicAdd(&g_cnt[edst[(size_t)i * g_stride]], 1);
}

__global__ void scan1_kernel() {
    __shared__ int sh[256];
    int t = threadIdx.x, b = blockIdx.x;
    int i = b * 256 + t;
    sh[t] = (i < NN) ? g_cnt[i] : 0;
    __syncthreads();
    for (int off = 128; off > 0; off >>= 1) {
        if (t < off) sh[t] += sh[t + off];
        __syncthreads();
    }
    if (t == 0) g_part[b] = sh[0];
}

__global__ void scan2_kernel(int nblk) {
    __shared__ int sh[256];
    int t = threadIdx.x;
    int v = (t < nblk) ? g_part[t] : 0;
    sh[t] = v;
    __syncthreads();
    for (int off = 1; off < 256; off <<= 1) {
        int u = (t >= off) ? sh[t - off] : 0;
        __syncthreads();
        sh[t] += u;
        __syncthreads();
    }
    if (t < nblk) g_part[t] = sh[t] - v;
}

__global__ void scan3_kernel() {
    __shared__ int sh[256];
    int t = threadIdx.x, b = blockIdx.x;
    int i = b * 256 + t;
    int c = (i < NN) ? g_cnt[i] : 0;
    sh[t] = c;
    __syncthreads();
    for (int off = 1; off < 256; off <<= 1) {
        int u = (t >= off) ? sh[t - off] : 0;
        __syncthreads();
        sh[t] += u;
        __syncthreads();
    }
    if (i < NN) g_rowptr[i] = g_part[b] + sh[t] - c;
    if (b == 0 && t == 0) g_rowptr[NN] = NE;
}

__global__ void scatter_kernel(const int* __restrict__ edst) {
    int i = blockIdx.x * blockDim.x + threadIdx.x;
    if (i >= NE) return;
    int d = edst[(size_t)i * g_stride];
    int pos = atomicAdd(&g_cur[d], 1);
    g_eid[g_rowptr[d] + pos] = i;
}

__global__ void sortsrc_kernel(const int* __restrict__ esrc) {
    int n = blockIdx.x * blockDim.x + threadIdx.x;
    if (n >= NN) return;
    int st = g_stride;
    int s = g_rowptr[n], e = g_rowptr[n + 1];
    for (int i = s + 1; i < e; i++) {
        int key = g_eid[i];
        int j = i - 1;
        while (j >= s && g_eid[j] > key) { g_eid[j + 1] = g_eid[j]; j--; }
        g_eid[j + 1] = key;
    }
    for (int i = s; i < e; i++) g_srcs[i] = esrc[(size_t)g_eid[i] * st];
}

// ---------------- weight prep (tf32-rounded copies) -------------------------
__global__ void repack_kernel(const float* __restrict__ W_post) {
    int idx = blockIdx.x * blockDim.x + threadIdx.x;
    if (idx >= 512 * 384) return;
    int k = idx / 384, j = idx % 384;
    int s = j >> 7, jj = j & 127;
    g_B2[idx] = rnd_tf32(W_post[(size_t)(128 + s * 512 + k) * 128 + jj]);
}

__global__ void roundw_kernel(const float* __restrict__ W_pre,
                              const float* __restrict__ W_post,
                              const float* __restrict__ W_mix) {
    int idx = blockIdx.x * blockDim.x + threadIdx.x;
    if (idx >= 4 * 16384) return;
    int m = idx >> 14, r = idx & 16383;
    float v;
    if (m == 0)      v = W_pre[r];
    else if (m == 1) v = W_pre[16384 + r];
    else if (m == 2) v = W_post[r];
    else             v = W_mix[r];
    g_Wr[idx] = rnd_tf32(v);
}

__global__ void round_h_kernel(const float* __restrict__ h) {
    int idx = blockIdx.x * blockDim.x + threadIdx.x;
    if (idx >= NN * 32) return;
    float4 v = ((const float4*)h)[idx];
    v.x = rnd_tf32(v.x); v.y = rnd_tf32(v.y);
    v.z = rnd_tf32(v.z); v.w = rnd_tf32(v.w);
    ((float4*)g_hr)[idx] = v;
}

// ---------------- tf32 MMA GEMM core, 2-stage cp.async pipeline ------------
// Operands are pre-rounded to tf32 bit patterns; the hot loop bit-passes them.
// mode 0: C = acc; 1: C = acc + bias; 2: C = res + leaky_relu(acc + bias)
__device__ __forceinline__ void mma_tf32(float* d, const uint32_t* a,
                                         const uint32_t* b) {
    asm volatile(
        "mma.sync.aligned.m16n8k8.row.col.f32.tf32.tf32.f32 "
        "{%0,%1,%2,%3}, {%4,%5,%6,%7}, {%8,%9}, {%0,%1,%2,%3};"
        : "+f"(d[0]), "+f"(d[1]), "+f"(d[2]), "+f"(d[3])
        : "r"(a[0]), "r"(a[1]), "r"(a[2]), "r"(a[3]), "r"(b[0]), "r"(b[1]));
}

#define ASTR 36
#define BSTR 136
#define A_STAGE (128 * ASTR)
#define B_STAGE (32 * BSTR)
#define SMEM_BYTES ((2 * A_STAGE + 2 * B_STAGE) * 4)   /* 71680 */

__device__ __forceinline__
void gemm_core(const float* __restrict__ A, int lda,
               const float* __restrict__ B, int ldb,
               float* __restrict__ C, int ldc,
               int M, int K, int mode,
               const float* __restrict__ bias,
               const float* __restrict__ res,
               int brow, int bcol, float* sm) {
    float* Asm = sm;
    float* Bsm = sm + 2 * A_STAGE;
    const int tid = threadIdx.x;
    const int wid = tid >> 5, lane = tid & 31;
    const int warpM = (wid >> 2) * 64;
    const int warpN = (wid & 3) * 32;
    const int r = lane >> 2;
    const int cq = lane & 3;

    float acc[4][4][4];
#pragma unroll
    for (int mt = 0; mt < 4; mt++)
#pragma unroll
        for (int nt = 0; nt < 4; nt++)
#pragma unroll
            for (int i = 0; i < 4; i++) acc[mt][nt][i] = 0.f;

    const int lm = tid >> 3;
    const int lk4 = (tid & 7) * 4;
    const int ln4 = lane * 4;
    const int nch = K >> 5;

    auto issue = [&](int ch, int st) {
        const int k0 = ch << 5;
        float* as = Asm + st * A_STAGE;
        float* bs = Bsm + st * B_STAGE;
#pragma unroll
        for (int i = 0; i < 4; i++) {
            int m = lm + i * 32;
            int grow = brow + m;
            int cl = (grow < M) ? grow : (M - 1);
            const float* gp = &A[(size_t)cl * lda + k0 + lk4];
            int sz = (grow < M) ? 16 : 0;
            uint32_t sa = smem_u32(&as[m * ASTR + lk4]);
            asm volatile("cp.async.cg.shared.global [%0], [%1], 16, %2;"
                         :: "r"(sa), "l"(gp), "r"(sz));
        }
#pragma unroll
        for (int i = 0; i < 4; i++) {
            int kk = wid + i * 8;
            const float* gp = &B[(size_t)(k0 + kk) * ldb + bcol + ln4];
            uint32_t sa = smem_u32(&bs[kk * BSTR + ln4]);
            asm volatile("cp.async.cg.shared.global [%0], [%1], 16;"
                         :: "r"(sa), "l"(gp));
        }
        asm volatile("cp.async.commit_group;");
    };

    issue(0, 0);
    for (int ch = 0; ch < nch; ch++) {
        if (ch + 1 < nch) {
            issue(ch + 1, (ch + 1) & 1);
            asm volatile("cp.async.wait_group 1;");
        } else {
            asm volatile("cp.async.wait_group 0;");
        }
        __syncthreads();
        const float* as = Asm + (ch & 1) * A_STAGE;
        const float* bs = Bsm + (ch & 1) * B_STAGE;
#pragma unroll
        for (int g = 0; g < 4; g++) {
            uint32_t af[4][4];
#pragma unroll
            for (int mt = 0; mt < 4; mt++) {
                const float* p0 = &as[(warpM + mt * 16 + r) * ASTR + g * 8 + cq];
                const float* p1 = p0 + 8 * ASTR;
                af[mt][0] = __float_as_uint(p0[0]);
                af[mt][1] = __float_as_uint(p1[0]);
                af[mt][2] = __float_as_uint(p0[4]);
                af[mt][3] = __float_as_uint(p1[4]);
            }
            uint32_t bf[4][2];
#pragma unroll
            for (int nt = 0; nt < 4; nt++) {
                int nb = warpN + nt * 8 + r;
                bf[nt][0] = __float_as_uint(bs[(g * 8 + cq) * BSTR + nb]);
                bf[nt][1] = __float_as_uint(bs[(g * 8 + cq + 4) * BSTR + nb]);
            }
#pragma unroll
            for (int mt = 0; mt < 4; mt++)
#pragma unroll
                for (int nt = 0; nt < 4; nt++)
                    mma_tf32(acc[mt][nt], af[mt], bf[nt]);
        }
        __syncthreads();
    }

#pragma unroll
    for (int mt = 0; mt < 4; mt++) {
        int row0 = brow + warpM + mt * 16 + r;
        int row1 = row0 + 8;
#pragma unroll
        for (int nt = 0; nt < 4; nt++) {
            int col = bcol + warpN + nt * 8 + 2 * cq;
            float o0 = acc[mt][nt][0], o1 = acc[mt][nt][1];
            float o2 = acc[mt][nt][2], o3 = acc[mt][nt][3];
            if (mode == 1) {
                float b0 = bias[col], b1 = bias[col + 1];
                o0 += b0; o1 += b1; o2 += b0; o3 += b1;
            } else if (mode == 2) {
                float b0 = bias[col], b1 = bias[col + 1];
                o0 += b0; o1 += b1; o2 += b0; o3 += b1;
                o0 = (o0 > 0.f) ? o0 : 0.01f * o0;
                o1 = (o1 > 0.f) ? o1 : 0.01f * o1;
                o2 = (o2 > 0.f) ? o2 : 0.01f * o2;
                o3 = (o3 > 0.f) ? o3 : 0.01f * o3;
                if (row0 < M) {
                    o0 += res[(size_t)row0 * ldc + col];
                    o1 += res[(size_t)row0 * ldc + col + 1];
                }
                if (row1 < M) {
                    o2 += res[(size_t)row1 * ldc + col];
                    o3 += res[(size_t)row1 * ldc + col + 1];
                }
            }
            if (row0 < M) *(float2*)&C[(size_t)row0 * ldc + col] = make_float2(o0, o1);
            if (row1 < M) *(float2*)&C[(size_t)row1 * ldc + col] = make_float2(o2, o3);
        }
    }
}

// generic wrapper (Y GEMM, final GEMM)
__global__ __launch_bounds__(256, 2)
void mma_gemm(const float* __restrict__ A, int lda,
              const float* __restrict__ B, int ldb,
              float* __restrict__ C, int ldc,
              int M, int K, int mode,
              const float* __restrict__ bias,
              const float* __restrict__ res) {
    extern __shared__ float sm[];
    gemm_core(A, lda, B, ldb, C, ldc, M, K, mode, bias, res,
              blockIdx.x * 128, blockIdx.y * 128, sm);
}

// merged P/Q/H0 wrapper: grid.y = 0 -> P, 1 -> Q (+b_pre), 2 -> H0
__global__ __launch_bounds__(256, 2)
void mma_gemm_pqh(const float* __restrict__ b_pre) {
    extern __shared__ float sm[];
    int y = blockIdx.y;
    const float* B = g_Wr + (size_t)y * 16384;
    float* C = (y == 0) ? g_P : (y == 1) ? g_Q : g_H0;
    gemm_core(g_hr, 128, B, 128, C, 128, NN, 128, (y == 1) ? 1 : 0, b_pre,
              nullptr, blockIdx.x * 128, 0, sm);
}

// ---------------- per-node multi-aggregator reduce -------------------------
// outputs tf32-rounded agg (feeds Y GEMM only)
__global__ __launch_bounds__(256)
void aggregate_kernel() {
    int gw = (blockIdx.x * blockDim.x + threadIdx.x) >> 5;
    int lane = threadIdx.x & 31;
    if (gw >= NN) return;
    const float4* P4 = (const float4*)g_P;
    const float4* Q4 = (const float4*)g_Q;
    float4 q = Q4[(size_t)gw * 32 + lane];
    int s = g_rowptr[gw], e = g_rowptr[gw + 1];
    float4 sm = make_float4(0.f, 0.f, 0.f, 0.f);
    float4 ss = make_float4(0.f, 0.f, 0.f, 0.f);
    float4 mx = make_float4(-3.4e38f, -3.4e38f, -3.4e38f, -3.4e38f);
    float4 mn = make_float4(3.4e38f, 3.4e38f, 3.4e38f, 3.4e38f);
    for (int i = s; i < e; i++) {
        int src = g_srcs[i];
        float4 p = P4[(size_t)src * 32 + lane];
        float ex = fmaxf(p.x + q.x, 0.f);
        float ey = fmaxf(p.y + q.y, 0.f);
        float ez = fmaxf(p.z + q.z, 0.f);
        float ew = fmaxf(p.w + q.w, 0.f);
        sm.x += ex; sm.y += ey; sm.z += ez; sm.w += ew;
        ss.x += ex * ex; ss.y += ey * ey; ss.z += ez * ez; ss.w += ew * ew;
        mx.x = fmaxf(mx.x, ex); mx.y = fmaxf(mx.y, ey);
        mx.z = fmaxf(mx.z, ez); mx.w = fmaxf(mx.w, ew);
        mn.x = fminf(mn.x, ex); mn.y = fminf(mn.y, ey);
        mn.z = fminf(mn.z, ez); mn.w = fminf(mn.w, ew);
    }
    float deg = (float)(e - s);
    float inv = 1.0f / deg;
    float4 mean = make_float4(sm.x * inv, sm.y * inv, sm.z * inv, sm.w * inv);
    float4 msq  = make_float4(ss.x * inv, ss.y * inv, ss.z * inv, ss.w * inv);
    float4 sd;
    sd.x = sqrtf(fmaxf(msq.x - mean.x * mean.x, 0.f) + 1e-5f);
    sd.y = sqrtf(fmaxf(msq.y - mean.y * mean.y, 0.f) + 1e-5f);
    sd.z = sqrtf(fmaxf(msq.z - mean.z * mean.z, 0.f) + 1e-5f);
    sd.w = sqrtf(fmaxf(msq.w - mean.w * mean.w, 0.f) + 1e-5f);
    mean.x = rnd_tf32(mean.x); mean.y = rnd_tf32(mean.y);
    mean.z = rnd_tf32(mean.z); mean.w = rnd_tf32(mean.w);
    mx.x = rnd_tf32(mx.x); mx.y = rnd_tf32(mx.y);
    mx.z = rnd_tf32(mx.z); mx.w = rnd_tf32(mx.w);
    mn.x = rnd_tf32(mn.x); mn.y = rnd_tf32(mn.y);
    mn.z = rnd_tf32(mn.z); mn.w = rnd_tf32(mn.w);
    sd.x = rnd_tf32(sd.x); sd.y = rnd_tf32(sd.y);
    sd.z = rnd_tf32(sd.z); sd.w = rnd_tf32(sd.w);
    float4* out = (float4*)(g_agg + (size_t)gw * 512);
    out[lane]      = mean;
    out[32 + lane] = mx;
    out[64 + lane] = mn;
    out[96 + lane] = sd;
    if (lane == 0) {
        float ld = logf(deg + 1.0f);
        g_sa[gw] = ld * (1.0f / AVG_D_LOG_F);
        g_sb[gw] = AVG_D_LOG_F / ld;
    }
}

// ---------------- combine: hp = relu(H0 + Y0 + a*Y1 + b*Y2 + b_post) -------
// outputs tf32-rounded hp (feeds final GEMM only)
__global__ void combine_kernel(const float* __restrict__ b_post) {
    int idx = blockIdx.x * blockDim.x + threadIdx.x;
    if (idx >= NN * 32) return;
    int n = idx >> 5, l = idx & 31;
    const float4* H04 = (const float4*)g_H0;
    const float4* Y4 = (const float4*)g_Y;
    const float4* bp4 = (const float4*)b_post;
    float a = g_sa[n], b = g_sb[n];
    float4 h0 = H04[idx];
    float4 y0 = Y4[(size_t)n * 96 + l];
    float4 y1 = Y4[(size_t)n * 96 + 32 + l];
    float4 y2 = Y4[(size_t)n * 96 + 64 + l];
    float4 bb = bp4[l];
    float4 v;
    v.x = rnd_tf32(fmaxf(h0.x + y0.x + a * y1.x + b * y2.x + bb.x, 0.f));
    v.y = rnd_tf32(fmaxf(h0.y + y0.y + a * y1.y + b * y2.y + bb.y, 0.f));
    v.z = rnd_tf32(fmaxf(h0.z + y0.z + a * y1.z + b * y2.z + bb.z, 0.f));
    v.w = rnd_tf32(fmaxf(h0.w + y0.w + a * y1.w + b * y2.w + bb.w, 0.f));
    ((float4*)g_hp)[idx] = v;
}

// ---------------- launch ---------------------------------------------------
extern "C" void kernel_launch(void* const* d_in, const int* in_sizes, int n_in,
                              void* d_out, int out_size) {
    const float* h      = (const float*)d_in[0];
    const int*   esrc   = (const int*)d_in[1];
    const int*   edst   = (const int*)d_in[2];
    const float* W_pre  = (const float*)d_in[3];
    const float* b_pre  = (const float*)d_in[4];
    const float* W_post = (const float*)d_in[5];
    const float* b_post = (const float*)d_in[6];
    const float* W_mix  = (const float*)d_in[7];
    const float* b_mix  = (const float*)d_in[8];
    float*       out    = (float*)d_out;

    float *AGG, *Y, *HP, *B2, *WR;
    cudaGetSymbolAddress((void**)&AGG, g_agg);
    cudaGetSymbolAddress((void**)&Y,   g_Y);
    cudaGetSymbolAddress((void**)&HP,  g_hp);
    cudaGetSymbolAddress((void**)&B2,  g_B2);
    cudaGetSymbolAddress((void**)&WR,  g_Wr);

    cudaFuncSetAttribute(mma_gemm, cudaFuncAttributeMaxDynamicSharedMemorySize,
                         SMEM_BYTES);
    cudaFuncSetAttribute(mma_gemm_pqh, cudaFuncAttributeMaxDynamicSharedMemorySize,
                         SMEM_BYTES);

    static cudaStream_t s2 = nullptr;
    static cudaEvent_t evFork = nullptr, evCsr = nullptr;
    if (s2 == nullptr) {
        cudaStreamCreateWithFlags(&s2, cudaStreamNonBlocking);
        cudaEventCreateWithFlags(&evFork, cudaEventDisableTiming);
        cudaEventCreateWithFlags(&evCsr, cudaEventDisableTiming);
    }

    const int nscan = (NN + 255) / 256;  // 196
    dim3 g1((NN + 127) / 128, 1);

    // ---- fork: side stream runs CSR chain + weight prep ----
    cudaEventRecord(evFork, 0);
    cudaStreamWaitEvent(s2, evFork, 0);

    zero_detect_kernel<<<(NN + 255) / 256, 256, 0, s2>>>(edst);
    hist_kernel<<<(NE + 255) / 256, 256, 0, s2>>>(edst);
    scan1_kernel<<<nscan, 256, 0, s2>>>();
    scan2_kernel<<<1, 256, 0, s2>>>(nscan);
    scan3_kernel<<<nscan, 256, 0, s2>>>();
    scatter_kernel<<<(NE + 255) / 256, 256, 0, s2>>>(edst);
    sortsrc_kernel<<<(NN + 127) / 128, 128, 0, s2>>>(esrc);
    repack_kernel<<<(512 * 384 + 255) / 256, 256, 0, s2>>>(W_post);
    cudaEventRecord(evCsr, s2);

    // ---- main stream: round inputs, then merged P/Q/H0 GEMM ----
    roundw_kernel<<<(4 * 16384 + 255) / 256, 256>>>(W_pre, W_post, W_mix);
    round_h_kernel<<<(NN * 32 + 255) / 256, 256>>>(h);

    dim3 gpqh((NN + 127) / 128, 3);
    mma_gemm_pqh<<<gpqh, 256, SMEM_BYTES>>>(b_pre);

    // join CSR, then aggregate
    cudaStreamWaitEvent(0, evCsr, 0);
    aggregate_kernel<<<(NN + 7) / 8, 256>>>();

    // Y = agg @ Bcat  (50000 x 512 x 384)
    dim3 g2((NN + 127) / 128, 3);
    mma_gemm<<<g2, 256, SMEM_BYTES>>>(AGG, 512, B2, 384, Y, 384, NN, 512, 0,
                                      nullptr, nullptr);

    combine_kernel<<<(NN * 32 + 255) / 256, 256>>>(b_post);

    // out = h + leaky_relu(hp @ W_mix + b_mix)
    mma_gemm<<<g1, 256, SMEM_BYTES>>>(HP, 128, WR + 3 * 16384, 128, out, 128,
                                      NN, 128, 2, b_mix, h);
}